// round 10
// baseline (speedup 1.0000x reference)
#include <cuda_runtime.h>
#include <cstdint>
#include <cstddef>

// ---------------------------------------------------------------------------
// Problem dims
// ---------------------------------------------------------------------------
#define BDIM   8192
#define DIN    2048
#define HDIM   2048
#define DOUT   1024
#define NCOMP  4
#define KDIM   2048      // inner dim of every GEMM
#define KC     64        // KDIM / 32  (k-chunks of 32)
#define NK     32        // KDIM / 64  (BK=64 iterations)

// ---------------------------------------------------------------------------
// Helpers (sm_103-safe)
// ---------------------------------------------------------------------------
__device__ __forceinline__ uint32_t smem_u32(const void* p) {
    uint32_t a;
    asm("{ .reg .u64 t; cvta.to.shared.u64 t, %1; cvt.u32.u64 %0, t; }"
        : "=r"(a) : "l"(p));
    return a;
}

__device__ __forceinline__ void cp_async16(uint32_t dst, const void* src) {
    asm volatile("cp.async.cg.shared.global [%0], [%1], 16;"
                 :: "r"(dst), "l"(__cvta_generic_to_global(src)));
}
#define CP_COMMIT() asm volatile("cp.async.commit_group;" ::: "memory")
#define CP_WAIT(n)  asm volatile("cp.async.wait_group %0;" :: "n"(n) : "memory")

// s8 IMMA: D(s32) += A(s8,16x32) * B(s8,32x8)
__device__ __forceinline__ void imma16832(int* d, const uint4& a,
                                          uint32_t b0, uint32_t b1) {
    asm volatile(
        "mma.sync.aligned.m16n8k32.row.col.s32.s8.s8.s32 "
        "{%0,%1,%2,%3}, {%4,%5,%6,%7}, {%8,%9}, {%0,%1,%2,%3};"
        : "+r"(d[0]), "+r"(d[1]), "+r"(d[2]), "+r"(d[3])
        : "r"(a.x), "r"(a.y), "r"(a.z), "r"(a.w), "r"(b0), "r"(b1));
}

// ---------------------------------------------------------------------------
// Scratch (__device__ globals; no cudaMalloc allowed)
// ---------------------------------------------------------------------------
__device__ __align__(16) char  g_w0qh[HDIM * DIN],  g_w0ql[HDIM * DIN];
__device__ __align__(16) char  g_w1qh[HDIM * HDIM], g_w1ql[HDIM * HDIM];
__device__ __align__(16) char  g_w2qh[DOUT * HDIM], g_w2ql[DOUT * HDIM];
__device__ __align__(16) char  g_aqh[BDIM * DIN],   g_aql[BDIM * DIN];
__device__ __align__(16) float g_effw[HDIM * DIN];      // reused per layer
__device__ __align__(16) float g_act[BDIM * HDIM];      // reused per layer
__device__ __align__(16) float g_sw0[HDIM], g_sw1[HDIM], g_sw2[DOUT];
__device__ __align__(16) float g_sa[BDIM];
__device__ __align__(16) float g_b0[HDIM], g_b1[HDIM], g_b2[DOUT];

// ---------------------------------------------------------------------------
// Mixture fold:  W_eff = sum_k softmax(ml)_k * (w_mu_k + exp(0.5 lv_k) w_n_k)
// ---------------------------------------------------------------------------
__device__ __forceinline__ void mix_coefs(const float* ml, const float* lv,
                                          float* cmu, float* cn) {
    float m[NCOMP], mx = -1e30f, s = 0.f, e[NCOMP];
    #pragma unroll
    for (int k = 0; k < NCOMP; k++) { m[k] = ml[k]; mx = fmaxf(mx, m[k]); }
    #pragma unroll
    for (int k = 0; k < NCOMP; k++) { e[k] = expf(m[k] - mx); s += e[k]; }
    #pragma unroll
    for (int k = 0; k < NCOMP; k++) {
        float w = e[k] / s;
        cmu[k] = w;
        cn[k]  = w * expf(0.5f * lv[k]);
    }
}

__global__ void fold_w_kernel(const float* __restrict__ wmu,
                              const float* __restrict__ wn,
                              const float* __restrict__ wlv,
                              const float* __restrict__ ml,
                              float* __restrict__ eff, int n) {
    __shared__ float cmu[NCOMP], cn[NCOMP];
    if (threadIdx.x == 0) mix_coefs(ml, wlv, cmu, cn);
    __syncthreads();
    int n4 = n >> 2;
    for (int i = blockIdx.x * blockDim.x + threadIdx.x; i < n4;
         i += gridDim.x * blockDim.x) {
        float4 acc = make_float4(0.f, 0.f, 0.f, 0.f);
        #pragma unroll
        for (int k = 0; k < NCOMP; k++) {
            float4 a = ((const float4*)wmu)[(size_t)k * n4 + i];
            float4 b = ((const float4*)wn)[(size_t)k * n4 + i];
            acc.x += cmu[k] * a.x + cn[k] * b.x;
            acc.y += cmu[k] * a.y + cn[k] * b.y;
            acc.z += cmu[k] * a.z + cn[k] * b.z;
            acc.w += cmu[k] * a.w + cn[k] * b.w;
        }
        ((float4*)eff)[i] = acc;
    }
}

__global__ void prep_bias_kernel(const float* __restrict__ bmu,
                                 const float* __restrict__ bn,
                                 const float* __restrict__ blv,
                                 const float* __restrict__ ml,
                                 float* __restrict__ out, int O) {
    __shared__ float cmu[NCOMP], cn[NCOMP];
    if (threadIdx.x == 0) mix_coefs(ml, blv, cmu, cn);
    __syncthreads();
    int o = blockIdx.x * blockDim.x + threadIdx.x;
    if (o < O) {
        float e = 0.f;
        #pragma unroll
        for (int k = 0; k < NCOMP; k++)
            e += cmu[k] * bmu[k * O + o] + cn[k] * bn[k * O + o];
        out[o] = e;
    }
}

// ---------------------------------------------------------------------------
// Per-row scale: s = max|row| / 127   (rows of width KDIM=2048)
// ---------------------------------------------------------------------------
__global__ void rowmax_kernel(const float* __restrict__ src,
                              float* __restrict__ scale) {
    __shared__ float red[8];
    int row = blockIdx.x, t = threadIdx.x;
    const float* p = src + (size_t)row * KDIM + t * 8;
    float4 a = *(const float4*)p;
    float4 b = *(const float4*)(p + 4);
    float m = fmaxf(fmaxf(fmaxf(fabsf(a.x), fabsf(a.y)), fmaxf(fabsf(a.z), fabsf(a.w))),
                    fmaxf(fmaxf(fabsf(b.x), fabsf(b.y)), fmaxf(fabsf(b.z), fabsf(b.w))));
    #pragma unroll
    for (int o = 16; o; o >>= 1) m = fmaxf(m, __shfl_xor_sync(0xffffffffu, m, o));
    if ((t & 31) == 0) red[t >> 5] = m;
    __syncthreads();
    if (t == 0) {
        #pragma unroll
        for (int w = 1; w < 8; w++) m = fmaxf(m, red[w]);
        float s = m * (1.f / 127.f);
        scale[row] = (s > 0.f) ? s : 1.f;
    }
}

// ---------------------------------------------------------------------------
// Double-int8 quantization of 4 consecutive values -> (qh word, ql word)
//   x ~= s * (qh + ql/252),  error <= s/504
// ---------------------------------------------------------------------------
__device__ __forceinline__ void quant4(const float4 v, float s,
                                       uint32_t& qh, uint32_t& ql) {
    float inv = 1.f / s;
    int h0 = min(max(__float2int_rn(v.x * inv), -127), 127);
    int h1 = min(max(__float2int_rn(v.y * inv), -127), 127);
    int h2 = min(max(__float2int_rn(v.z * inv), -127), 127);
    int h3 = min(max(__float2int_rn(v.w * inv), -127), 127);
    int l0 = min(max(__float2int_rn((v.x - s * h0) * inv * 252.f), -127), 127);
    int l1 = min(max(__float2int_rn((v.y - s * h1) * inv * 252.f), -127), 127);
    int l2 = min(max(__float2int_rn((v.z - s * h2) * inv * 252.f), -127), 127);
    int l3 = min(max(__float2int_rn((v.w - s * h3) * inv * 252.f), -127), 127);
    qh = (h0 & 255) | ((h1 & 255) << 8) | ((h2 & 255) << 16) | ((h3 & 255) << 24);
    ql = (l0 & 255) | ((l1 & 255) << 8) | ((l2 & 255) << 16) | ((l3 & 255) << 24);
}

// ---------------------------------------------------------------------------
// pack_a: [M, K] fp32 -> IMMA A-fragment-packed int8 (qh, ql).
// Tile (t=m/16, c=k/32): 32 lanes x 16B; lane l holds
//   a0=(row g, k 4tg..), a1=(g+8, ..), a2=(g, k+16..), a3=(g+8, k+16..)
//   with g = t*16 + (l>>2), tg = l&3.  Out uint4 index == global thread id.
// ---------------------------------------------------------------------------
__global__ void pack_a_kernel(const float* __restrict__ src,
                              const float* __restrict__ sc,
                              uint4* __restrict__ qh, uint4* __restrict__ ql) {
    int gid = blockIdx.x * blockDim.x + threadIdx.x;
    int l = gid & 31, rest = gid >> 5;
    int c = rest & (KC - 1), t = rest >> 6;
    int row = t * 16 + (l >> 2);
    int kb = c * 32 + 4 * (l & 3);
    const float* p0 = src + (size_t)row * KDIM + kb;
    const float* p1 = src + (size_t)(row + 8) * KDIM + kb;
    float s0 = sc[row], s1 = sc[row + 8];
    uint32_t h0, q0, h1, q1, h2, q2, h3, q3;
    quant4(*(const float4*)p0, s0, h0, q0);
    quant4(*(const float4*)p1, s1, h1, q1);
    quant4(*(const float4*)(p0 + 16), s0, h2, q2);
    quant4(*(const float4*)(p1 + 16), s1, h3, q3);
    qh[gid] = make_uint4(h0, h1, h2, h3);
    ql[gid] = make_uint4(q0, q1, q2, q3);
}

// ---------------------------------------------------------------------------
// pack_w: [N, K] fp32 -> IMMA B-fragment-packed int8.
// Tile (u=n/8, c=k/32): 32 lanes x 8B; lane l holds
//   b0=(n u*8+(l>>2), k 4tg..), b1=(same n, k+16..). Out uint2 index == gid.
// ---------------------------------------------------------------------------
__global__ void pack_w_kernel(const float* __restrict__ src,
                              const float* __restrict__ sc,
                              uint2* __restrict__ qh, uint2* __restrict__ ql) {
    int gid = blockIdx.x * blockDim.x + threadIdx.x;
    int l = gid & 31, rest = gid >> 5;
    int c = rest & (KC - 1), u = rest >> 6;
    int n = u * 8 + (l >> 2);
    int kb = c * 32 + 4 * (l & 3);
    const float* p = src + (size_t)n * KDIM + kb;
    float s = sc[n];
    uint32_t h0, q0, h1, q1;
    quant4(*(const float4*)p, s, h0, q0);
    quant4(*(const float4*)(p + 16), s, h1, q1);
    qh[gid] = make_uint2(h0, h1);
    ql[gid] = make_uint2(q0, q1);
}

// ---------------------------------------------------------------------------
// s8 GEMM:  out[B, O] = s_a s_w (HH + MID/252) + bias  (+optional ReLU)
// CTA 128x128, BK=64 (2 k32 chunks/iter), 8 warps (2x4), warp tile 64x32.
// 2 cp.async stages x 32 KB. Operands pre-packed -> plain LDS.128/LDS.64.
// ---------------------------------------------------------------------------
#define NT 256
#define STG 32768
#define GEMM_SMEM_TOTAL (2 * STG + 1536)

__global__ void __launch_bounds__(NT, 1)
gemm_s8(const char* __restrict__ Aqh, const char* __restrict__ Aql,
        const float* __restrict__ s_a,
        const char* __restrict__ Wqh, const char* __restrict__ Wql,
        const float* __restrict__ s_w,
        const float* __restrict__ bias,
        int Odim, int relu, float* __restrict__ out) {
    extern __shared__ char smem[];
    const uint32_t sb = smem_u32(smem);
    const int tid = threadIdx.x, wid = tid >> 5, l = tid & 31;
    const int n0 = blockIdx.x * 128, m0 = blockIdx.y * 128;
    const int wm = (wid >> 2) * 64;     // m band (0 / 64)
    const int wnb = (wid & 3) * 32;     // n band (0/32/64/96)

    float* s_w_sm = (float*)(smem + 2 * STG);
    float* bias_sm = s_w_sm + 128;
    float* s_a_sm = bias_sm + 128;
    if (tid < 128) {
        s_w_sm[tid] = s_w[n0 + tid];
        bias_sm[tid] = bias[n0 + tid];
        s_a_sm[tid] = s_a[m0 + tid];
    }

    int acc_hh[4][4][4], acc_md[4][4][4];
    #pragma unroll
    for (int i = 0; i < 4; i++)
        #pragma unroll
        for (int j = 0; j < 4; j++)
            #pragma unroll
            for (int q = 0; q < 4; q++) { acc_hh[i][j][q] = 0; acc_md[i][j][q] = 0; }

    // stage layout: Aqh @0 (8KB), Aql @8192, Wqh @16384, Wql @24576
    auto issue = [&](int s, int it) {
        uint32_t base = sb + s * STG;
        #pragma unroll
        for (int j = 0; j < 2; j++) {
            int c = tid + j * NT;
            {   // A: 8 m-tiles x 1024B contiguous (2 chunks)
                int mt = c >> 6;
                uint32_t off = (uint32_t)(c & 63) * 16;
                size_t g = ((size_t)((m0 >> 4) + mt) * (KC * 512)) +
                           (size_t)it * 1024 + off;
                cp_async16(base + mt * 1024 + off, Aqh + g);
                cp_async16(base + 8192 + mt * 1024 + off, Aql + g);
            }
            {   // W: 16 n-tiles x 512B contiguous (2 chunks)
                int u = c >> 5;
                uint32_t off = (uint32_t)(c & 31) * 16;
                size_t g = ((size_t)((n0 >> 3) + u) * (KC * 256)) +
                           (size_t)it * 512 + off;
                cp_async16(base + 16384 + u * 512 + off, Wqh + g);
                cp_async16(base + 24576 + u * 512 + off, Wql + g);
            }
        }
    };

    issue(0, 0);
    CP_COMMIT();

    for (int it = 0; it < NK; ++it) {
        CP_WAIT(0);
        __syncthreads();                 // data visible + WAR on other stage
        if (it + 1 < NK) {
            issue((it + 1) & 1, it + 1);
            CP_COMMIT();
        }

        const char* st = smem + (it & 1) * STG;
        #pragma unroll
        for (int cs = 0; cs < 2; cs++) {
            uint4 ah[4], al[4];
            #pragma unroll
            for (int mf = 0; mf < 4; mf++) {
                const char* pa = st + ((wm >> 4) + mf) * 1024 + cs * 512 + l * 16;
                ah[mf] = *(const uint4*)pa;
                al[mf] = *(const uint4*)(pa + 8192);
            }
            #pragma unroll
            for (int nf = 0; nf < 4; nf++) {
                const char* pw = st + 16384 + ((wnb >> 3) + nf) * 512 + cs * 256 + l * 8;
                uint2 bh = *(const uint2*)pw;
                uint2 bl = *(const uint2*)(pw + 8192);
                #pragma unroll
                for (int mf = 0; mf < 4; mf++)
                    imma16832(acc_hh[mf][nf], ah[mf], bh.x, bh.y);
                #pragma unroll
                for (int mf = 0; mf < 4; mf++)
                    imma16832(acc_md[mf][nf], ah[mf], bl.x, bl.y);
                #pragma unroll
                for (int mf = 0; mf < 4; mf++)
                    imma16832(acc_md[mf][nf], al[mf], bh.x, bh.y);
            }
        }
    }

    const float inv252 = 1.f / 252.f;
    #pragma unroll
    for (int mf = 0; mf < 4; mf++) {
        int rl = wm + mf * 16 + (l >> 2);
        int r0 = m0 + rl;
        float sa0 = s_a_sm[rl], sa1 = s_a_sm[rl + 8];
        #pragma unroll
        for (int nf = 0; nf < 4; nf++) {
            int cl = wnb + nf * 8 + 2 * (l & 3);
            float sw0 = s_w_sm[cl], sw1 = s_w_sm[cl + 1];
            float bv0 = bias_sm[cl], bv1 = bias_sm[cl + 1];
            float v00 = ((float)acc_hh[mf][nf][0] + (float)acc_md[mf][nf][0] * inv252) * sa0 * sw0 + bv0;
            float v01 = ((float)acc_hh[mf][nf][1] + (float)acc_md[mf][nf][1] * inv252) * sa0 * sw1 + bv1;
            float v10 = ((float)acc_hh[mf][nf][2] + (float)acc_md[mf][nf][2] * inv252) * sa1 * sw0 + bv0;
            float v11 = ((float)acc_hh[mf][nf][3] + (float)acc_md[mf][nf][3] * inv252) * sa1 * sw1 + bv1;
            if (relu) {
                v00 = fmaxf(v00, 0.f); v01 = fmaxf(v01, 0.f);
                v10 = fmaxf(v10, 0.f); v11 = fmaxf(v11, 0.f);
            }
            *(float2*)(out + (size_t)r0 * Odim + n0 + cl) = make_float2(v00, v01);
            *(float2*)(out + (size_t)(r0 + 8) * Odim + n0 + cl) = make_float2(v10, v11);
        }
    }
}

// ---------------------------------------------------------------------------
// Row softmax (in-place), 1024 cols, 256 threads/row
// ---------------------------------------------------------------------------
__global__ void softmax_kernel(float* __restrict__ io) {
    __shared__ float red[8];
    int b = blockIdx.x;
    float* row = io + (size_t)b * DOUT;
    int t = threadIdx.x;
    float v[4];
    float m = -1e30f;
    #pragma unroll
    for (int i = 0; i < 4; i++) { v[i] = row[t + 256 * i]; m = fmaxf(m, v[i]); }
    #pragma unroll
    for (int o = 16; o; o >>= 1) m = fmaxf(m, __shfl_xor_sync(0xffffffffu, m, o));
    if ((t & 31) == 0) red[t >> 5] = m;
    __syncthreads();
    m = red[0];
    #pragma unroll
    for (int w = 1; w < 8; w++) m = fmaxf(m, red[w]);
    float s = 0.f;
    #pragma unroll
    for (int i = 0; i < 4; i++) { v[i] = expf(v[i] - m); s += v[i]; }
    #pragma unroll
    for (int o = 16; o; o >>= 1) s += __shfl_xor_sync(0xffffffffu, s, o);
    __syncthreads();
    if ((t & 31) == 0) red[t >> 5] = s;
    __syncthreads();
    s = red[0];
    #pragma unroll
    for (int w = 1; w < 8; w++) s += red[w];
    float inv = 1.0f / s;
    #pragma unroll
    for (int i = 0; i < 4; i++) row[t + 256 * i] = v[i] * inv;
}

// ---------------------------------------------------------------------------
// Launcher
// ---------------------------------------------------------------------------
extern "C" void kernel_launch(void* const* d_in, const int* in_sizes, int n_in,
                              void* d_out, int out_size) {
    (void)in_sizes; (void)n_in; (void)out_size;
    const float* x   = (const float*)d_in[0];
    const float* wmu[3] = {(const float*)d_in[1],  (const float*)d_in[8],  (const float*)d_in[15]};
    const float* bmu[3] = {(const float*)d_in[2],  (const float*)d_in[9],  (const float*)d_in[16]};
    const float* wlv[3] = {(const float*)d_in[3],  (const float*)d_in[10], (const float*)d_in[17]};
    const float* blv[3] = {(const float*)d_in[4],  (const float*)d_in[11], (const float*)d_in[18]};
    const float* ml[3]  = {(const float*)d_in[5],  (const float*)d_in[12], (const float*)d_in[19]};
    const float* wn[3]  = {(const float*)d_in[6],  (const float*)d_in[13], (const float*)d_in[20]};
    const float* bn[3]  = {(const float*)d_in[7],  (const float*)d_in[14], (const float*)d_in[21]};

    void *w0h, *w0l, *w1h, *w1l, *w2h, *w2l, *aqh, *aql;
    void *effw, *act, *sw0, *sw1, *sw2, *sa, *b0, *b1, *b2;
    cudaGetSymbolAddress(&w0h, g_w0qh); cudaGetSymbolAddress(&w0l, g_w0ql);
    cudaGetSymbolAddress(&w1h, g_w1qh); cudaGetSymbolAddress(&w1l, g_w1ql);
    cudaGetSymbolAddress(&w2h, g_w2qh); cudaGetSymbolAddress(&w2l, g_w2ql);
    cudaGetSymbolAddress(&aqh, g_aqh);  cudaGetSymbolAddress(&aql, g_aql);
    cudaGetSymbolAddress(&effw, g_effw); cudaGetSymbolAddress(&act, g_act);
    cudaGetSymbolAddress(&sw0, g_sw0);  cudaGetSymbolAddress(&sw1, g_sw1);
    cudaGetSymbolAddress(&sw2, g_sw2);  cudaGetSymbolAddress(&sa, g_sa);
    cudaGetSymbolAddress(&b0, g_b0);    cudaGetSymbolAddress(&b1, g_b1);
    cudaGetSymbolAddress(&b2, g_b2);

    cudaFuncSetAttribute(gemm_s8,
                         cudaFuncAttributeMaxDynamicSharedMemorySize, GEMM_SMEM_TOTAL);

    // --- weights: fold -> rowmax -> fragment-pack (effw buffer reused) ---
    fold_w_kernel<<<2048, 256>>>(wmu[0], wn[0], wlv[0], ml[0], (float*)effw, HDIM * DIN);
    rowmax_kernel<<<HDIM, 256>>>((const float*)effw, (float*)sw0);
    pack_w_kernel<<<(HDIM / 8) * KC * 32 / 256, 256>>>(
        (const float*)effw, (const float*)sw0, (uint2*)w0h, (uint2*)w0l);

    fold_w_kernel<<<2048, 256>>>(wmu[1], wn[1], wlv[1], ml[1], (float*)effw, HDIM * HDIM);
    rowmax_kernel<<<HDIM, 256>>>((const float*)effw, (float*)sw1);
    pack_w_kernel<<<(HDIM / 8) * KC * 32 / 256, 256>>>(
        (const float*)effw, (const float*)sw1, (uint2*)w1h, (uint2*)w1l);

    fold_w_kernel<<<1024, 256>>>(wmu[2], wn[2], wlv[2], ml[2], (float*)effw, DOUT * HDIM);
    rowmax_kernel<<<DOUT, 256>>>((const float*)effw, (float*)sw2);
    pack_w_kernel<<<(DOUT / 8) * KC * 32 / 256, 256>>>(
        (const float*)effw, (const float*)sw2, (uint2*)w2h, (uint2*)w2l);

    prep_bias_kernel<<<HDIM / 256, 256>>>(bmu[0], bn[0], blv[0], ml[0], (float*)b0, HDIM);
    prep_bias_kernel<<<HDIM / 256, 256>>>(bmu[1], bn[1], blv[1], ml[1], (float*)b1, HDIM);
    prep_bias_kernel<<<DOUT / 256, 256>>>(bmu[2], bn[2], blv[2], ml[2], (float*)b2, DOUT);

    // --- layer 0 ---
    rowmax_kernel<<<BDIM, 256>>>(x, (float*)sa);
    pack_a_kernel<<<(BDIM / 16) * KC * 32 / 256, 256>>>(
        x, (const float*)sa, (uint4*)aqh, (uint4*)aql);
    gemm_s8<<<dim3(HDIM / 128, BDIM / 128), NT, GEMM_SMEM_TOTAL>>>(
        (const char*)aqh, (const char*)aql, (const float*)sa,
        (const char*)w0h, (const char*)w0l, (const float*)sw0,
        (const float*)b0, HDIM, 1, (float*)act);

    // --- layer 1 ---
    rowmax_kernel<<<BDIM, 256>>>((const float*)act, (float*)sa);
    pack_a_kernel<<<(BDIM / 16) * KC * 32 / 256, 256>>>(
        (const float*)act, (const float*)sa, (uint4*)aqh, (uint4*)aql);
    gemm_s8<<<dim3(HDIM / 128, BDIM / 128), NT, GEMM_SMEM_TOTAL>>>(
        (const char*)aqh, (const char*)aql, (const float*)sa,
        (const char*)w1h, (const char*)w1l, (const float*)sw1,
        (const float*)b1, HDIM, 1, (float*)act);

    // --- layer 2 -> logits in d_out ---
    rowmax_kernel<<<BDIM, 256>>>((const float*)act, (float*)sa);
    pack_a_kernel<<<(BDIM / 16) * KC * 32 / 256, 256>>>(
        (const float*)act, (const float*)sa, (uint4*)aqh, (uint4*)aql);
    gemm_s8<<<dim3(DOUT / 128, BDIM / 128), NT, GEMM_SMEM_TOTAL>>>(
        (const char*)aqh, (const char*)aql, (const float*)sa,
        (const char*)w2h, (const char*)w2l, (const float*)sw2,
        (const float*)b2, DOUT, 0, (float*)d_out);

    // --- softmax ---
    softmax_kernel<<<BDIM, 256>>>((float*)d_out);
}

// round 11
// speedup vs baseline: 1.9342x; 1.9342x over previous
#include <cuda_runtime.h>
#include <cuda_bf16.h>
#include <cstdint>
#include <cstddef>

// ---------------------------------------------------------------------------
// Problem dims
// ---------------------------------------------------------------------------
#define BDIM   8192
#define DIN    2048
#define HDIM   2048
#define DOUT   1024
#define NCOMP  4

// ---------------------------------------------------------------------------
// Helpers (sm_103-safe)
// ---------------------------------------------------------------------------
__device__ __forceinline__ uint32_t smem_u32(const void* p) {
    uint32_t a;
    asm("{ .reg .u64 t; cvta.to.shared.u64 t, %1; cvt.u32.u64 %0, t; }"
        : "=r"(a) : "l"(p));
    return a;
}

#define SMEM_SWIZZLE_128B(o) ((o) ^ (((o) >> 3) & 0x70))

__device__ __forceinline__ void cp_async16(uint32_t dst, const void* src) {
    asm volatile("cp.async.cg.shared.global [%0], [%1], 16;"
                 :: "r"(dst), "l"(__cvta_generic_to_global(src)));
}
#define CP_COMMIT() asm volatile("cp.async.commit_group;" ::: "memory")
#define CP_WAIT(n)  asm volatile("cp.async.wait_group %0;" :: "n"(n) : "memory")

__device__ __forceinline__ void ldsm4(uint32_t* r, uint32_t addr) {
    asm volatile("ldmatrix.sync.aligned.m8n8.x4.shared.b16 {%0,%1,%2,%3}, [%4];"
                 : "=r"(r[0]), "=r"(r[1]), "=r"(r[2]), "=r"(r[3]) : "r"(addr));
}

__device__ __forceinline__ void mma16816(float* d, const uint32_t* a,
                                         uint32_t b0, uint32_t b1) {
    asm volatile(
        "mma.sync.aligned.m16n8k16.row.col.f32.bf16.bf16.f32 "
        "{%0,%1,%2,%3}, {%4,%5,%6,%7}, {%8,%9}, {%0,%1,%2,%3};"
        : "+f"(d[0]), "+f"(d[1]), "+f"(d[2]), "+f"(d[3])
        : "r"(a[0]), "r"(a[1]), "r"(a[2]), "r"(a[3]), "r"(b0), "r"(b1));
}

// ---------------------------------------------------------------------------
// Scratch buffers (__device__ globals; no cudaMalloc allowed)
// ---------------------------------------------------------------------------
__device__ __align__(16) __nv_bfloat16 g_wh0[HDIM * DIN];
__device__ __align__(16) __nv_bfloat16 g_wl0[HDIM * DIN];
__device__ __align__(16) __nv_bfloat16 g_wh1[HDIM * HDIM];
__device__ __align__(16) __nv_bfloat16 g_wl1[HDIM * HDIM];
__device__ __align__(16) __nv_bfloat16 g_wh2[DOUT * HDIM];
__device__ __align__(16) __nv_bfloat16 g_wl2[DOUT * HDIM];
__device__ __align__(16) float g_b0[HDIM];
__device__ __align__(16) float g_b1[HDIM];
__device__ __align__(16) float g_b2[DOUT];
__device__ __align__(16) __nv_bfloat16 g_a0h[BDIM * DIN];
__device__ __align__(16) __nv_bfloat16 g_a0l[BDIM * DIN];
__device__ __align__(16) __nv_bfloat16 g_a1h[BDIM * HDIM];
__device__ __align__(16) __nv_bfloat16 g_a1l[BDIM * HDIM];
__device__ __align__(16) __nv_bfloat16 g_a2h[BDIM * HDIM];
__device__ __align__(16) __nv_bfloat16 g_a2l[BDIM * HDIM];

// ---------------------------------------------------------------------------
// Prep kernels: fold mixture into effective bf16 hi/lo weights + fp32 bias
// ---------------------------------------------------------------------------
__device__ __forceinline__ void mix_coefs(const float* ml, const float* lv,
                                          float* cmu, float* cn) {
    float m[NCOMP], mx = -1e30f, s = 0.f, e[NCOMP];
    #pragma unroll
    for (int k = 0; k < NCOMP; k++) { m[k] = ml[k]; mx = fmaxf(mx, m[k]); }
    #pragma unroll
    for (int k = 0; k < NCOMP; k++) { e[k] = expf(m[k] - mx); s += e[k]; }
    #pragma unroll
    for (int k = 0; k < NCOMP; k++) {
        float w = e[k] / s;
        cmu[k] = w;
        cn[k]  = w * expf(0.5f * lv[k]);
    }
}

__global__ void prep_weights_kernel(const float* __restrict__ wmu,
                                    const float* __restrict__ wn,
                                    const float* __restrict__ wlv,
                                    const float* __restrict__ ml,
                                    __nv_bfloat16* __restrict__ whi,
                                    __nv_bfloat16* __restrict__ wlo,
                                    int n) {
    __shared__ float cmu[NCOMP], cn[NCOMP];
    if (threadIdx.x == 0) mix_coefs(ml, wlv, cmu, cn);
    __syncthreads();
    int n4 = n >> 2;
    for (int i = blockIdx.x * blockDim.x + threadIdx.x; i < n4;
         i += gridDim.x * blockDim.x) {
        float4 acc = make_float4(0.f, 0.f, 0.f, 0.f);
        #pragma unroll
        for (int k = 0; k < NCOMP; k++) {
            float4 a = ((const float4*)wmu)[(size_t)k * n4 + i];
            float4 b = ((const float4*)wn)[(size_t)k * n4 + i];
            acc.x += cmu[k] * a.x + cn[k] * b.x;
            acc.y += cmu[k] * a.y + cn[k] * b.y;
            acc.z += cmu[k] * a.z + cn[k] * b.z;
            acc.w += cmu[k] * a.w + cn[k] * b.w;
        }
        __nv_bfloat16 h0 = __float2bfloat16(acc.x);
        __nv_bfloat16 h1 = __float2bfloat16(acc.y);
        __nv_bfloat16 h2 = __float2bfloat16(acc.z);
        __nv_bfloat16 h3 = __float2bfloat16(acc.w);
        __nv_bfloat16 l0 = __float2bfloat16(acc.x - __bfloat162float(h0));
        __nv_bfloat16 l1 = __float2bfloat16(acc.y - __bfloat162float(h1));
        __nv_bfloat16 l2 = __float2bfloat16(acc.z - __bfloat162float(h2));
        __nv_bfloat16 l3 = __float2bfloat16(acc.w - __bfloat162float(h3));
        ((__nv_bfloat162*)whi)[2 * (size_t)i]     = __halves2bfloat162(h0, h1);
        ((__nv_bfloat162*)whi)[2 * (size_t)i + 1] = __halves2bfloat162(h2, h3);
        ((__nv_bfloat162*)wlo)[2 * (size_t)i]     = __halves2bfloat162(l0, l1);
        ((__nv_bfloat162*)wlo)[2 * (size_t)i + 1] = __halves2bfloat162(l2, l3);
    }
}

__global__ void prep_bias_kernel(const float* __restrict__ bmu,
                                 const float* __restrict__ bn,
                                 const float* __restrict__ blv,
                                 const float* __restrict__ ml,
                                 float* __restrict__ out, int O) {
    __shared__ float cmu[NCOMP], cn[NCOMP];
    if (threadIdx.x == 0) mix_coefs(ml, blv, cmu, cn);
    __syncthreads();
    int o = blockIdx.x * blockDim.x + threadIdx.x;
    if (o < O) {
        float e = 0.f;
        #pragma unroll
        for (int k = 0; k < NCOMP; k++)
            e += cmu[k] * bmu[k * O + o] + cn[k] * bn[k * O + o];
        out[o] = e;
    }
}

__global__ void split_x_kernel(const float* __restrict__ x,
                               __nv_bfloat16* __restrict__ xh,
                               __nv_bfloat16* __restrict__ xl, int n) {
    int n4 = n >> 2;
    for (int i = blockIdx.x * blockDim.x + threadIdx.x; i < n4;
         i += gridDim.x * blockDim.x) {
        float4 v = ((const float4*)x)[i];
        __nv_bfloat16 h0 = __float2bfloat16(v.x);
        __nv_bfloat16 h1 = __float2bfloat16(v.y);
        __nv_bfloat16 h2 = __float2bfloat16(v.z);
        __nv_bfloat16 h3 = __float2bfloat16(v.w);
        __nv_bfloat16 l0 = __float2bfloat16(v.x - __bfloat162float(h0));
        __nv_bfloat16 l1 = __float2bfloat16(v.y - __bfloat162float(h1));
        __nv_bfloat16 l2 = __float2bfloat16(v.z - __bfloat162float(h2));
        __nv_bfloat16 l3 = __float2bfloat16(v.w - __bfloat162float(h3));
        ((__nv_bfloat162*)xh)[2 * (size_t)i]     = __halves2bfloat162(h0, h1);
        ((__nv_bfloat162*)xh)[2 * (size_t)i + 1] = __halves2bfloat162(h2, h3);
        ((__nv_bfloat162*)xl)[2 * (size_t)i]     = __halves2bfloat162(l0, l1);
        ((__nv_bfloat162*)xl)[2 * (size_t)i + 1] = __halves2bfloat162(l2, l3);
    }
}

// ---------------------------------------------------------------------------
// mma.sync GEMM:  C[B,O] = A[B,I] @ W[O,I]^T + bias   (split bf16 hi/lo)
// Template MFRAG: warp m-tile = MFRAG*16, CTA BM = MFRAG*32 (2 m-bands).
//   MFRAG=4 -> 128x128 CTA tile (L0/L1), MFRAG=2 -> 64x128 (L2 tail fix).
// BK=64, 8 warps (2x4), warp tile (MFRAG*16)x32.
// 3 cp.async stages: wait_group(1) keeps 2 loads in flight (tail: wait 0).
// ---------------------------------------------------------------------------
#define BN 128
#define BK 64
#define NT 256

template <int MFRAG>
__global__ void __launch_bounds__(NT, 1)
gemm_split_bf16(const __nv_bfloat16* __restrict__ Ah,
                const __nv_bfloat16* __restrict__ Al,
                const __nv_bfloat16* __restrict__ Wh,
                const __nv_bfloat16* __restrict__ Wl,
                const float* __restrict__ bias,
                int Idim, int Odim, int relu_split,
                __nv_bfloat16* __restrict__ Oh,
                __nv_bfloat16* __restrict__ Ol,
                float* __restrict__ Of) {
    constexpr int BM = MFRAG * 32;
    constexpr int OFF_AL = BM * 128;             // A hi bytes
    constexpr int OFF_WH = 2 * BM * 128;
    constexpr int OFF_WL = 2 * BM * 128 + 16384; // W hi = 128*128 = 16 KB
    constexpr int STAGE = 2 * BM * 128 + 32768;

    extern __shared__ char smem[];
    const uint32_t sb = smem_u32(smem);
    const int tid = threadIdx.x;
    const int wid = tid >> 5, l = tid & 31;
    const int n0 = blockIdx.x * BN, m0 = blockIdx.y * BM;
    const int wm = (wid >> 2) * (MFRAG * 16);  // m band
    const int wn = (wid & 3) * 32;             // n band
    const int lm = l >> 3, lr = l & 7;

    float acc[MFRAG][4][4];
    #pragma unroll
    for (int i = 0; i < MFRAG; i++)
        #pragma unroll
        for (int j = 0; j < 4; j++)
            #pragma unroll
            for (int q = 0; q < 4; q++) acc[i][j][q] = 0.f;

    const int nk = Idim / BK;

    auto issue = [&](int s, int k0) {
        uint32_t base = sb + s * STAGE;
        #pragma unroll
        for (int j = 0; j < MFRAG; j++) {      // A: BM*8 chunks per array
            int c = tid + j * NT;
            int row = c >> 3, col = c & 7;
            uint32_t so = SMEM_SWIZZLE_128B((uint32_t)(row * 128 + col * 16));
            size_t g = (size_t)(m0 + row) * Idim + k0 + col * 8;
            cp_async16(base + so, Ah + g);
            cp_async16(base + OFF_AL + so, Al + g);
        }
        #pragma unroll
        for (int j = 0; j < 4; j++) {          // W: 1024 chunks per array
            int c = tid + j * NT;
            int row = c >> 3, col = c & 7;
            uint32_t so = SMEM_SWIZZLE_128B((uint32_t)(row * 128 + col * 16));
            size_t g = (size_t)(n0 + row) * Idim + k0 + col * 8;
            cp_async16(base + OFF_WH + so, Wh + g);
            cp_async16(base + OFF_WL + so, Wl + g);
        }
    };

    issue(0, 0);      CP_COMMIT();
    issue(1, BK);     CP_COMMIT();

    for (int it = 0; it < nk; ++it) {
        if (it + 1 < nk) CP_WAIT(1);   // group `it` complete (in-order)
        else             CP_WAIT(0);   // tail: only group nk-1 pending
        __syncthreads();               // visibility + WAR on slot (it+2)%3
        if (it + 2 < nk) {
            issue((it + 2) % 3, (it + 2) * BK);
            CP_COMMIT();
        }

        uint32_t bA = sb + (it % 3) * STAGE;
        #pragma unroll
        for (int kk = 0; kk < 4; kk++) {
            uint32_t ah[MFRAG][4], al[MFRAG][4];
            #pragma unroll
            for (int mf = 0; mf < MFRAG; mf++) {
                uint32_t off = SMEM_SWIZZLE_128B(
                    (uint32_t)((wm + mf * 16 + (lm & 1) * 8 + lr) * 128 +
                               (kk * 2 + (lm >> 1)) * 16));
                ldsm4(ah[mf], bA + off);
                ldsm4(al[mf], bA + OFF_AL + off);
            }
            #pragma unroll
            for (int nf2 = 0; nf2 < 2; nf2++) {
                uint32_t off = SMEM_SWIZZLE_128B(
                    (uint32_t)((wn + nf2 * 16 + (lm >> 1) * 8 + lr) * 128 +
                               (kk * 2 + (lm & 1)) * 16));
                uint32_t bh[4], bl[4];
                ldsm4(bh, bA + OFF_WH + off);
                ldsm4(bl, bA + OFF_WL + off);
                #pragma unroll
                for (int mf = 0; mf < MFRAG; mf++) {
                    mma16816(acc[mf][2 * nf2],     ah[mf], bh[0], bh[1]);
                    mma16816(acc[mf][2 * nf2 + 1], ah[mf], bh[2], bh[3]);
                }
                #pragma unroll
                for (int mf = 0; mf < MFRAG; mf++) {
                    mma16816(acc[mf][2 * nf2],     ah[mf], bl[0], bl[1]);
                    mma16816(acc[mf][2 * nf2 + 1], ah[mf], bl[2], bl[3]);
                }
                #pragma unroll
                for (int mf = 0; mf < MFRAG; mf++) {
                    mma16816(acc[mf][2 * nf2],     al[mf], bh[0], bh[1]);
                    mma16816(acc[mf][2 * nf2 + 1], al[mf], bh[2], bh[3]);
                }
            }
        }
    }

    // Epilogue
    const int cb = n0 + wn;
    if (relu_split) {
        #pragma unroll
        for (int mf = 0; mf < MFRAG; mf++) {
            int r0 = m0 + wm + mf * 16 + (l >> 2);
            #pragma unroll
            for (int nf = 0; nf < 4; nf++) {
                int col = cb + nf * 8 + 2 * (l & 3);
                float2 bv = *(const float2*)(bias + col);
                float v0 = fmaxf(acc[mf][nf][0] + bv.x, 0.f);
                float v1 = fmaxf(acc[mf][nf][1] + bv.y, 0.f);
                float v2 = fmaxf(acc[mf][nf][2] + bv.x, 0.f);
                float v3 = fmaxf(acc[mf][nf][3] + bv.y, 0.f);
                __nv_bfloat16 h0 = __float2bfloat16(v0);
                __nv_bfloat16 h1 = __float2bfloat16(v1);
                __nv_bfloat16 h2 = __float2bfloat16(v2);
                __nv_bfloat16 h3 = __float2bfloat16(v3);
                __nv_bfloat16 q0 = __float2bfloat16(v0 - __bfloat162float(h0));
                __nv_bfloat16 q1 = __float2bfloat16(v1 - __bfloat162float(h1));
                __nv_bfloat16 q2 = __float2bfloat16(v2 - __bfloat162float(h2));
                __nv_bfloat16 q3 = __float2bfloat16(v3 - __bfloat162float(h3));
                *(__nv_bfloat162*)(Oh + (size_t)r0 * Odim + col) = __halves2bfloat162(h0, h1);
                *(__nv_bfloat162*)(Oh + (size_t)(r0 + 8) * Odim + col) = __halves2bfloat162(h2, h3);
                *(__nv_bfloat162*)(Ol + (size_t)r0 * Odim + col) = __halves2bfloat162(q0, q1);
                *(__nv_bfloat162*)(Ol + (size_t)(r0 + 8) * Odim + col) = __halves2bfloat162(q2, q3);
            }
        }
    } else {
        #pragma unroll
        for (int mf = 0; mf < MFRAG; mf++) {
            int r0 = m0 + wm + mf * 16 + (l >> 2);
            #pragma unroll
            for (int nf = 0; nf < 4; nf++) {
                int col = cb + nf * 8 + 2 * (l & 3);
                float2 bv = *(const float2*)(bias + col);
                float2 o0 = make_float2(acc[mf][nf][0] + bv.x, acc[mf][nf][1] + bv.y);
                float2 o1 = make_float2(acc[mf][nf][2] + bv.x, acc[mf][nf][3] + bv.y);
                *(float2*)(Of + (size_t)r0 * Odim + col) = o0;
                *(float2*)(Of + (size_t)(r0 + 8) * Odim + col) = o1;
            }
        }
    }
}

#define SMEM_M4 (3 * (2 * 128 * 128 + 32768))   // 192 KB
#define SMEM_M2 (3 * (2 * 64 * 128 + 32768))    // 144 KB

// ---------------------------------------------------------------------------
// Row softmax (in-place), 1024 cols, 256 threads/row
// ---------------------------------------------------------------------------
__global__ void softmax_kernel(float* __restrict__ io) {
    __shared__ float red[8];
    int b = blockIdx.x;
    float* row = io + (size_t)b * DOUT;
    int t = threadIdx.x;
    float v[4];
    float m = -1e30f;
    #pragma unroll
    for (int i = 0; i < 4; i++) { v[i] = row[t + 256 * i]; m = fmaxf(m, v[i]); }
    #pragma unroll
    for (int o = 16; o; o >>= 1) m = fmaxf(m, __shfl_xor_sync(0xffffffffu, m, o));
    if ((t & 31) == 0) red[t >> 5] = m;
    __syncthreads();
    m = red[0];
    #pragma unroll
    for (int w = 1; w < 8; w++) m = fmaxf(m, red[w]);
    float s = 0.f;
    #pragma unroll
    for (int i = 0; i < 4; i++) { v[i] = expf(v[i] - m); s += v[i]; }
    #pragma unroll
    for (int o = 16; o; o >>= 1) s += __shfl_xor_sync(0xffffffffu, s, o);
    __syncthreads();
    if ((t & 31) == 0) red[t >> 5] = s;
    __syncthreads();
    s = red[0];
    #pragma unroll
    for (int w = 1; w < 8; w++) s += red[w];
    float inv = 1.0f / s;
    #pragma unroll
    for (int i = 0; i < 4; i++) row[t + 256 * i] = v[i] * inv;
}

// ---------------------------------------------------------------------------
// Launcher
// ---------------------------------------------------------------------------
extern "C" void kernel_launch(void* const* d_in, const int* in_sizes, int n_in,
                              void* d_out, int out_size) {
    (void)in_sizes; (void)n_in; (void)out_size;
    const float* x   = (const float*)d_in[0];
    const float* wmu[3] = {(const float*)d_in[1],  (const float*)d_in[8],  (const float*)d_in[15]};
    const float* bmu[3] = {(const float*)d_in[2],  (const float*)d_in[9],  (const float*)d_in[16]};
    const float* wlv[3] = {(const float*)d_in[3],  (const float*)d_in[10], (const float*)d_in[17]};
    const float* blv[3] = {(const float*)d_in[4],  (const float*)d_in[11], (const float*)d_in[18]};
    const float* ml[3]  = {(const float*)d_in[5],  (const float*)d_in[12], (const float*)d_in[19]};
    const float* wn[3]  = {(const float*)d_in[6],  (const float*)d_in[13], (const float*)d_in[20]};
    const float* bn[3]  = {(const float*)d_in[7],  (const float*)d_in[14], (const float*)d_in[21]};

    void *wh0, *wl0, *wh1, *wl1, *wh2, *wl2, *b0, *b1, *b2;
    void *a0h, *a0l, *a1h, *a1l, *a2h, *a2l;
    cudaGetSymbolAddress(&wh0, g_wh0); cudaGetSymbolAddress(&wl0, g_wl0);
    cudaGetSymbolAddress(&wh1, g_wh1); cudaGetSymbolAddress(&wl1, g_wl1);
    cudaGetSymbolAddress(&wh2, g_wh2); cudaGetSymbolAddress(&wl2, g_wl2);
    cudaGetSymbolAddress(&b0, g_b0);   cudaGetSymbolAddress(&b1, g_b1);
    cudaGetSymbolAddress(&b2, g_b2);
    cudaGetSymbolAddress(&a0h, g_a0h); cudaGetSymbolAddress(&a0l, g_a0l);
    cudaGetSymbolAddress(&a1h, g_a1h); cudaGetSymbolAddress(&a1l, g_a1l);
    cudaGetSymbolAddress(&a2h, g_a2h); cudaGetSymbolAddress(&a2l, g_a2l);

    cudaFuncSetAttribute(gemm_split_bf16<4>,
                         cudaFuncAttributeMaxDynamicSharedMemorySize, SMEM_M4);
    cudaFuncSetAttribute(gemm_split_bf16<2>,
                         cudaFuncAttributeMaxDynamicSharedMemorySize, SMEM_M2);

    // prep
    prep_weights_kernel<<<2048, 256>>>(wmu[0], wn[0], wlv[0], ml[0],
                                       (__nv_bfloat16*)wh0, (__nv_bfloat16*)wl0, HDIM * DIN);
    prep_bias_kernel<<<HDIM / 256, 256>>>(bmu[0], bn[0], blv[0], ml[0], (float*)b0, HDIM);
    split_x_kernel<<<2048, 256>>>(x, (__nv_bfloat16*)a0h, (__nv_bfloat16*)a0l, BDIM * DIN);
    prep_weights_kernel<<<2048, 256>>>(wmu[1], wn[1], wlv[1], ml[1],
                                       (__nv_bfloat16*)wh1, (__nv_bfloat16*)wl1, HDIM * HDIM);
    prep_bias_kernel<<<HDIM / 256, 256>>>(bmu[1], bn[1], blv[1], ml[1], (float*)b1, HDIM);

    // layer 0: grid (16, 64) = 1024 CTAs, 128x128 tile
    gemm_split_bf16<4><<<dim3(HDIM / BN, BDIM / 128), NT, SMEM_M4>>>(
        (const __nv_bfloat16*)a0h, (const __nv_bfloat16*)a0l,
        (const __nv_bfloat16*)wh0, (const __nv_bfloat16*)wl0,
        (const float*)b0, DIN, HDIM, 1,
        (__nv_bfloat16*)a1h, (__nv_bfloat16*)a1l, nullptr);

    prep_weights_kernel<<<2048, 256>>>(wmu[2], wn[2], wlv[2], ml[2],
                                       (__nv_bfloat16*)wh2, (__nv_bfloat16*)wl2, DOUT * HDIM);
    prep_bias_kernel<<<DOUT / 256, 256>>>(bmu[2], bn[2], blv[2], ml[2], (float*)b2, DOUT);

    // layer 1: grid (16, 64)
    gemm_split_bf16<4><<<dim3(HDIM / BN, BDIM / 128), NT, SMEM_M4>>>(
        (const __nv_bfloat16*)a1h, (const __nv_bfloat16*)a1l,
        (const __nv_bfloat16*)wh1, (const __nv_bfloat16*)wl1,
        (const float*)b1, HDIM, HDIM, 1,
        (__nv_bfloat16*)a2h, (__nv_bfloat16*)a2l, nullptr);

    // layer 2 -> fp32 logits: 64x128 tile, grid (8, 128) = 1024 CTAs
    gemm_split_bf16<2><<<dim3(DOUT / BN, BDIM / 64), NT, SMEM_M2>>>(
        (const __nv_bfloat16*)a2h, (const __nv_bfloat16*)a2l,
        (const __nv_bfloat16*)wh2, (const __nv_bfloat16*)wl2,
        (const float*)b2, HDIM, DOUT, 0,
        nullptr, nullptr, (float*)d_out);

    // softmax in place
    softmax_kernel<<<BDIM, 256>>>((float*)d_out);
}

// round 12
// speedup vs baseline: 2.9585x; 1.5295x over previous
#include <cuda_runtime.h>
#include <cuda_bf16.h>
#include <cstdint>
#include <cstddef>

// ---------------------------------------------------------------------------
// Problem dims
// ---------------------------------------------------------------------------
#define BDIM   8192
#define DIN    2048
#define HDIM   2048
#define DOUT   1024
#define NCOMP  4

// ---------------------------------------------------------------------------
// Helpers (sm_103-safe)
// ---------------------------------------------------------------------------
__device__ __forceinline__ uint32_t smem_u32(const void* p) {
    uint32_t a;
    asm("{ .reg .u64 t; cvta.to.shared.u64 t, %1; cvt.u32.u64 %0, t; }"
        : "=r"(a) : "l"(p));
    return a;
}

#define SMEM_SWIZZLE_128B(o) ((o) ^ (((o) >> 3) & 0x70))

__device__ __forceinline__ void cp_async16(uint32_t dst, const void* src) {
    asm volatile("cp.async.cg.shared.global [%0], [%1], 16;"
                 :: "r"(dst), "l"(__cvta_generic_to_global(src)));
}
#define CP_COMMIT() asm volatile("cp.async.commit_group;" ::: "memory")
#define CP_WAIT(n)  asm volatile("cp.async.wait_group %0;" :: "n"(n) : "memory")

__device__ __forceinline__ void ldsm4(uint32_t* r, uint32_t addr) {
    asm volatile("ldmatrix.sync.aligned.m8n8.x4.shared.b16 {%0,%1,%2,%3}, [%4];"
                 : "=r"(r[0]), "=r"(r[1]), "=r"(r[2]), "=r"(r[3]) : "r"(addr));
}

__device__ __forceinline__ void mma16816(float* d, const uint32_t* a,
                                         uint32_t b0, uint32_t b1) {
    asm volatile(
        "mma.sync.aligned.m16n8k16.row.col.f32.bf16.bf16.f32 "
        "{%0,%1,%2,%3}, {%4,%5,%6,%7}, {%8,%9}, {%0,%1,%2,%3};"
        : "+f"(d[0]), "+f"(d[1]), "+f"(d[2]), "+f"(d[3])
        : "r"(a[0]), "r"(a[1]), "r"(a[2]), "r"(a[3]), "r"(b0), "r"(b1));
}

// ---------------------------------------------------------------------------
// Scratch buffers (__device__ globals; no cudaMalloc allowed)
// ---------------------------------------------------------------------------
__device__ __align__(16) __nv_bfloat16 g_wh0[HDIM * DIN];
__device__ __align__(16) __nv_bfloat16 g_wl0[HDIM * DIN];
__device__ __align__(16) __nv_bfloat16 g_wh1[HDIM * HDIM];
__device__ __align__(16) __nv_bfloat16 g_wl1[HDIM * HDIM];
__device__ __align__(16) __nv_bfloat16 g_wh2[DOUT * HDIM];
__device__ __align__(16) __nv_bfloat16 g_wl2[DOUT * HDIM];
__device__ __align__(16) float g_b0[HDIM];
__device__ __align__(16) float g_b1[HDIM];
__device__ __align__(16) float g_b2[DOUT];
__device__ __align__(16) __nv_bfloat16 g_a0h[BDIM * DIN];
__device__ __align__(16) __nv_bfloat16 g_a0l[BDIM * DIN];
__device__ __align__(16) __nv_bfloat16 g_a1h[BDIM * HDIM];
__device__ __align__(16) __nv_bfloat16 g_a1l[BDIM * HDIM];
__device__ __align__(16) __nv_bfloat16 g_a2h[BDIM * HDIM];
__device__ __align__(16) __nv_bfloat16 g_a2l[BDIM * HDIM];

// ---------------------------------------------------------------------------
// Prep kernels: fold mixture into effective bf16 hi/lo weights + fp32 bias
// ---------------------------------------------------------------------------
__device__ __forceinline__ void mix_coefs(const float* ml, const float* lv,
                                          float* cmu, float* cn) {
    float m[NCOMP], mx = -1e30f, s = 0.f, e[NCOMP];
    #pragma unroll
    for (int k = 0; k < NCOMP; k++) { m[k] = ml[k]; mx = fmaxf(mx, m[k]); }
    #pragma unroll
    for (int k = 0; k < NCOMP; k++) { e[k] = expf(m[k] - mx); s += e[k]; }
    #pragma unroll
    for (int k = 0; k < NCOMP; k++) {
        float w = e[k] / s;
        cmu[k] = w;
        cn[k]  = w * expf(0.5f * lv[k]);
    }
}

__global__ void prep_weights_kernel(const float* __restrict__ wmu,
                                    const float* __restrict__ wn,
                                    const float* __restrict__ wlv,
                                    const float* __restrict__ ml,
                                    __nv_bfloat16* __restrict__ whi,
                                    __nv_bfloat16* __restrict__ wlo,
                                    int n) {
    __shared__ float cmu[NCOMP], cn[NCOMP];
    if (threadIdx.x == 0) mix_coefs(ml, wlv, cmu, cn);
    __syncthreads();
    int n4 = n >> 2;
    for (int i = blockIdx.x * blockDim.x + threadIdx.x; i < n4;
         i += gridDim.x * blockDim.x) {
        float4 acc = make_float4(0.f, 0.f, 0.f, 0.f);
        #pragma unroll
        for (int k = 0; k < NCOMP; k++) {
            float4 a = ((const float4*)wmu)[(size_t)k * n4 + i];
            float4 b = ((const float4*)wn)[(size_t)k * n4 + i];
            acc.x += cmu[k] * a.x + cn[k] * b.x;
            acc.y += cmu[k] * a.y + cn[k] * b.y;
            acc.z += cmu[k] * a.z + cn[k] * b.z;
            acc.w += cmu[k] * a.w + cn[k] * b.w;
        }
        __nv_bfloat16 h0 = __float2bfloat16(acc.x);
        __nv_bfloat16 h1 = __float2bfloat16(acc.y);
        __nv_bfloat16 h2 = __float2bfloat16(acc.z);
        __nv_bfloat16 h3 = __float2bfloat16(acc.w);
        __nv_bfloat16 l0 = __float2bfloat16(acc.x - __bfloat162float(h0));
        __nv_bfloat16 l1 = __float2bfloat16(acc.y - __bfloat162float(h1));
        __nv_bfloat16 l2 = __float2bfloat16(acc.z - __bfloat162float(h2));
        __nv_bfloat16 l3 = __float2bfloat16(acc.w - __bfloat162float(h3));
        ((__nv_bfloat162*)whi)[2 * (size_t)i]     = __halves2bfloat162(h0, h1);
        ((__nv_bfloat162*)whi)[2 * (size_t)i + 1] = __halves2bfloat162(h2, h3);
        ((__nv_bfloat162*)wlo)[2 * (size_t)i]     = __halves2bfloat162(l0, l1);
        ((__nv_bfloat162*)wlo)[2 * (size_t)i + 1] = __halves2bfloat162(l2, l3);
    }
}

__global__ void prep_bias_kernel(const float* __restrict__ bmu,
                                 const float* __restrict__ bn,
                                 const float* __restrict__ blv,
                                 const float* __restrict__ ml,
                                 float* __restrict__ out, int O) {
    __shared__ float cmu[NCOMP], cn[NCOMP];
    if (threadIdx.x == 0) mix_coefs(ml, blv, cmu, cn);
    __syncthreads();
    int o = blockIdx.x * blockDim.x + threadIdx.x;
    if (o < O) {
        float e = 0.f;
        #pragma unroll
        for (int k = 0; k < NCOMP; k++)
            e += cmu[k] * bmu[k * O + o] + cn[k] * bn[k * O + o];
        out[o] = e;
    }
}

__global__ void split_x_kernel(const float* __restrict__ x,
                               __nv_bfloat16* __restrict__ xh,
                               __nv_bfloat16* __restrict__ xl, int n) {
    int n4 = n >> 2;
    for (int i = blockIdx.x * blockDim.x + threadIdx.x; i < n4;
         i += gridDim.x * blockDim.x) {
        float4 v = ((const float4*)x)[i];
        __nv_bfloat16 h0 = __float2bfloat16(v.x);
        __nv_bfloat16 h1 = __float2bfloat16(v.y);
        __nv_bfloat16 h2 = __float2bfloat16(v.z);
        __nv_bfloat16 h3 = __float2bfloat16(v.w);
        __nv_bfloat16 l0 = __float2bfloat16(v.x - __bfloat162float(h0));
        __nv_bfloat16 l1 = __float2bfloat16(v.y - __bfloat162float(h1));
        __nv_bfloat16 l2 = __float2bfloat16(v.z - __bfloat162float(h2));
        __nv_bfloat16 l3 = __float2bfloat16(v.w - __bfloat162float(h3));
        ((__nv_bfloat162*)xh)[2 * (size_t)i]     = __halves2bfloat162(h0, h1);
        ((__nv_bfloat162*)xh)[2 * (size_t)i + 1] = __halves2bfloat162(h2, h3);
        ((__nv_bfloat162*)xl)[2 * (size_t)i]     = __halves2bfloat162(l0, l1);
        ((__nv_bfloat162*)xl)[2 * (size_t)i + 1] = __halves2bfloat162(l2, l3);
    }
}

// ---------------------------------------------------------------------------
// mma.sync GEMM:  C[B,O] = A[B,I] @ W[O,I]^T + bias   (split bf16 hi/lo)
// EXACT R9 pipeline: 2 cp.async stages, ONE __syncthreads per iter,
// static dual-buffer stage addressing ((it & 1) * STAGE).
// Template MFRAG: CTA tile (MFRAG*32) x 128; MFRAG=4 for L0/L1 (128x128),
// MFRAG=2 for L2 (64x128 -> 1024 CTAs -> 98.8% placement vs 86.5%).
// ---------------------------------------------------------------------------
#define BN 128
#define BK 64
#define NT 256

template <int MFRAG>
__global__ void __launch_bounds__(NT, 1)
gemm_split_bf16(const __nv_bfloat16* __restrict__ Ah,
                const __nv_bfloat16* __restrict__ Al,
                const __nv_bfloat16* __restrict__ Wh,
                const __nv_bfloat16* __restrict__ Wl,
                const float* __restrict__ bias,
                int Idim, int Odim, int relu_split,
                __nv_bfloat16* __restrict__ Oh,
                __nv_bfloat16* __restrict__ Ol,
                float* __restrict__ Of) {
    constexpr int BM = MFRAG * 32;
    constexpr int OFF_AL = BM * 128;              // bytes of A-hi tile
    constexpr int OFF_WH = 2 * BM * 128;
    constexpr int OFF_WL = 2 * BM * 128 + 16384;  // W-hi tile = 16 KB
    constexpr int STAGE  = 2 * BM * 128 + 32768;  // MFRAG=4: 64 KB, =2: 48 KB

    extern __shared__ char smem[];
    const uint32_t sb = smem_u32(smem);
    const int tid = threadIdx.x;
    const int wid = tid >> 5, l = tid & 31;
    const int n0 = blockIdx.x * BN, m0 = blockIdx.y * BM;
    const int wm = (wid >> 2) * (MFRAG * 16);  // m band
    const int wn = (wid & 3) * 32;             // n band
    const int lm = l >> 3, lr = l & 7;

    float acc[MFRAG][4][4];
    #pragma unroll
    for (int i = 0; i < MFRAG; i++)
        #pragma unroll
        for (int j = 0; j < 4; j++)
            #pragma unroll
            for (int q = 0; q < 4; q++) acc[i][j][q] = 0.f;

    const int nk = Idim / BK;

    auto issue = [&](int s, int k0) {
        uint32_t base = sb + s * STAGE;
        #pragma unroll
        for (int j = 0; j < MFRAG; j++) {      // A: BM*8 16B chunks per array
            int c = tid + j * NT;
            int row = c >> 3, col = c & 7;
            uint32_t so = SMEM_SWIZZLE_128B((uint32_t)(row * 128 + col * 16));
            size_t g = (size_t)(m0 + row) * Idim + k0 + col * 8;
            cp_async16(base + so, Ah + g);
            cp_async16(base + OFF_AL + so, Al + g);
        }
        #pragma unroll
        for (int j = 0; j < 4; j++) {          // W: 1024 chunks per array
            int c = tid + j * NT;
            int row = c >> 3, col = c & 7;
            uint32_t so = SMEM_SWIZZLE_128B((uint32_t)(row * 128 + col * 16));
            size_t g = (size_t)(n0 + row) * Idim + k0 + col * 8;
            cp_async16(base + OFF_WH + so, Wh + g);
            cp_async16(base + OFF_WL + so, Wl + g);
        }
    };

    issue(0, 0);
    CP_COMMIT();

    for (int it = 0; it < nk; ++it) {
        CP_WAIT(0);          // only group `it` pending -> stage ready
        __syncthreads();     // visibility + WAR on stage (it+1)&1
        if (it + 1 < nk) {
            issue((it + 1) & 1, (it + 1) * BK);
            CP_COMMIT();
        }

        uint32_t bA = sb + (it & 1) * STAGE;
        #pragma unroll
        for (int kk = 0; kk < 4; kk++) {
            uint32_t ah[MFRAG][4], al[MFRAG][4];
            #pragma unroll
            for (int mf = 0; mf < MFRAG; mf++) {
                uint32_t off = SMEM_SWIZZLE_128B(
                    (uint32_t)((wm + mf * 16 + (lm & 1) * 8 + lr) * 128 +
                               (kk * 2 + (lm >> 1)) * 16));
                ldsm4(ah[mf], bA + off);
                ldsm4(al[mf], bA + OFF_AL + off);
            }
            #pragma unroll
            for (int nf2 = 0; nf2 < 2; nf2++) {
                uint32_t off = SMEM_SWIZZLE_128B(
                    (uint32_t)((wn + nf2 * 16 + (lm >> 1) * 8 + lr) * 128 +
                               (kk * 2 + (lm & 1)) * 16));
                uint32_t bh[4], bl[4];
                ldsm4(bh, bA + OFF_WH + off);
                ldsm4(bl, bA + OFF_WL + off);
                #pragma unroll
                for (int mf = 0; mf < MFRAG; mf++) {
                    mma16816(acc[mf][2 * nf2],     ah[mf], bh[0], bh[1]);
                    mma16816(acc[mf][2 * nf2 + 1], ah[mf], bh[2], bh[3]);
                }
                #pragma unroll
                for (int mf = 0; mf < MFRAG; mf++) {
                    mma16816(acc[mf][2 * nf2],     ah[mf], bl[0], bl[1]);
                    mma16816(acc[mf][2 * nf2 + 1], ah[mf], bl[2], bl[3]);
                }
                #pragma unroll
                for (int mf = 0; mf < MFRAG; mf++) {
                    mma16816(acc[mf][2 * nf2],     al[mf], bh[0], bh[1]);
                    mma16816(acc[mf][2 * nf2 + 1], al[mf], bh[2], bh[3]);
                }
            }
        }
    }

    // Epilogue
    const int cb = n0 + wn;
    if (relu_split) {
        #pragma unroll
        for (int mf = 0; mf < MFRAG; mf++) {
            int r0 = m0 + wm + mf * 16 + (l >> 2);
            #pragma unroll
            for (int nf = 0; nf < 4; nf++) {
                int col = cb + nf * 8 + 2 * (l & 3);
                float2 bv = *(const float2*)(bias + col);
                float v0 = fmaxf(acc[mf][nf][0] + bv.x, 0.f);
                float v1 = fmaxf(acc[mf][nf][1] + bv.y, 0.f);
                float v2 = fmaxf(acc[mf][nf][2] + bv.x, 0.f);
                float v3 = fmaxf(acc[mf][nf][3] + bv.y, 0.f);
                __nv_bfloat16 h0 = __float2bfloat16(v0);
                __nv_bfloat16 h1 = __float2bfloat16(v1);
                __nv_bfloat16 h2 = __float2bfloat16(v2);
                __nv_bfloat16 h3 = __float2bfloat16(v3);
                __nv_bfloat16 q0 = __float2bfloat16(v0 - __bfloat162float(h0));
                __nv_bfloat16 q1 = __float2bfloat16(v1 - __bfloat162float(h1));
                __nv_bfloat16 q2 = __float2bfloat16(v2 - __bfloat162float(h2));
                __nv_bfloat16 q3 = __float2bfloat16(v3 - __bfloat162float(h3));
                *(__nv_bfloat162*)(Oh + (size_t)r0 * Odim + col) = __halves2bfloat162(h0, h1);
                *(__nv_bfloat162*)(Oh + (size_t)(r0 + 8) * Odim + col) = __halves2bfloat162(h2, h3);
                *(__nv_bfloat162*)(Ol + (size_t)r0 * Odim + col) = __halves2bfloat162(q0, q1);
                *(__nv_bfloat162*)(Ol + (size_t)(r0 + 8) * Odim + col) = __halves2bfloat162(q2, q3);
            }
        }
    } else {
        #pragma unroll
        for (int mf = 0; mf < MFRAG; mf++) {
            int r0 = m0 + wm + mf * 16 + (l >> 2);
            #pragma unroll
            for (int nf = 0; nf < 4; nf++) {
                int col = cb + nf * 8 + 2 * (l & 3);
                float2 bv = *(const float2*)(bias + col);
                float2 o0 = make_float2(acc[mf][nf][0] + bv.x, acc[mf][nf][1] + bv.y);
                float2 o1 = make_float2(acc[mf][nf][2] + bv.x, acc[mf][nf][3] + bv.y);
                *(float2*)(Of + (size_t)r0 * Odim + col) = o0;
                *(float2*)(Of + (size_t)(r0 + 8) * Odim + col) = o1;
            }
        }
    }
}

#define SMEM_M4 (2 * (2 * 128 * 128 + 32768))   // 128 KB (exactly R9)
#define SMEM_M2 (2 * (2 * 64 * 128 + 32768))    // 96 KB

// ---------------------------------------------------------------------------
// Row softmax (in-place), 1024 cols, 256 threads/row
// ---------------------------------------------------------------------------
__global__ void softmax_kernel(float* __restrict__ io) {
    __shared__ float red[8];
    int b = blockIdx.x;
    float* row = io + (size_t)b * DOUT;
    int t = threadIdx.x;
    float v[4];
    float m = -1e30f;
    #pragma unroll
    for (int i = 0; i < 4; i++) { v[i] = row[t + 256 * i]; m = fmaxf(m, v[i]); }
    #pragma unroll
    for (int o = 16; o; o >>= 1) m = fmaxf(m, __shfl_xor_sync(0xffffffffu, m, o));
    if ((t & 31) == 0) red[t >> 5] = m;
    __syncthreads();
    m = red[0];
    #pragma unroll
    for (int w = 1; w < 8; w++) m = fmaxf(m, red[w]);
    float s = 0.f;
    #pragma unroll
    for (int i = 0; i < 4; i++) { v[i] = expf(v[i] - m); s += v[i]; }
    #pragma unroll
    for (int o = 16; o; o >>= 1) s += __shfl_xor_sync(0xffffffffu, s, o);
    __syncthreads();
    if ((t & 31) == 0) red[t >> 5] = s;
    __syncthreads();
    s = red[0];
    #pragma unroll
    for (int w = 1; w < 8; w++) s += red[w];
    float inv = 1.0f / s;
    #pragma unroll
    for (int i = 0; i < 4; i++) row[t + 256 * i] = v[i] * inv;
}

// ---------------------------------------------------------------------------
// Launcher
// ---------------------------------------------------------------------------
extern "C" void kernel_launch(void* const* d_in, const int* in_sizes, int n_in,
                              void* d_out, int out_size) {
    (void)in_sizes; (void)n_in; (void)out_size;
    const float* x   = (const float*)d_in[0];
    const float* wmu[3] = {(const float*)d_in[1],  (const float*)d_in[8],  (const float*)d_in[15]};
    const float* bmu[3] = {(const float*)d_in[2],  (const float*)d_in[9],  (const float*)d_in[16]};
    const float* wlv[3] = {(const float*)d_in[3],  (const float*)d_in[10], (const float*)d_in[17]};
    const float* blv[3] = {(const float*)d_in[4],  (const float*)d_in[11], (const float*)d_in[18]};
    const float* ml[3]  = {(const float*)d_in[5],  (const float*)d_in[12], (const float*)d_in[19]};
    const float* wn[3]  = {(const float*)d_in[6],  (const float*)d_in[13], (const float*)d_in[20]};
    const float* bn[3]  = {(const float*)d_in[7],  (const float*)d_in[14], (const float*)d_in[21]};

    void *wh0, *wl0, *wh1, *wl1, *wh2, *wl2, *b0, *b1, *b2;
    void *a0h, *a0l, *a1h, *a1l, *a2h, *a2l;
    cudaGetSymbolAddress(&wh0, g_wh0); cudaGetSymbolAddress(&wl0, g_wl0);
    cudaGetSymbolAddress(&wh1, g_wh1); cudaGetSymbolAddress(&wl1, g_wl1);
    cudaGetSymbolAddress(&wh2, g_wh2); cudaGetSymbolAddress(&wl2, g_wl2);
    cudaGetSymbolAddress(&b0, g_b0);   cudaGetSymbolAddress(&b1, g_b1);
    cudaGetSymbolAddress(&b2, g_b2);
    cudaGetSymbolAddress(&a0h, g_a0h); cudaGetSymbolAddress(&a0l, g_a0l);
    cudaGetSymbolAddress(&a1h, g_a1h); cudaGetSymbolAddress(&a1l, g_a1l);
    cudaGetSymbolAddress(&a2h, g_a2h); cudaGetSymbolAddress(&a2l, g_a2l);

    cudaFuncSetAttribute(gemm_split_bf16<4>,
                         cudaFuncAttributeMaxDynamicSharedMemorySize, SMEM_M4);
    cudaFuncSetAttribute(gemm_split_bf16<2>,
                         cudaFuncAttributeMaxDynamicSharedMemorySize, SMEM_M2);

    // prep
    prep_weights_kernel<<<2048, 256>>>(wmu[0], wn[0], wlv[0], ml[0],
                                       (__nv_bfloat16*)wh0, (__nv_bfloat16*)wl0, HDIM * DIN);
    prep_bias_kernel<<<HDIM / 256, 256>>>(bmu[0], bn[0], blv[0], ml[0], (float*)b0, HDIM);
    split_x_kernel<<<2048, 256>>>(x, (__nv_bfloat16*)a0h, (__nv_bfloat16*)a0l, BDIM * DIN);
    prep_weights_kernel<<<2048, 256>>>(wmu[1], wn[1], wlv[1], ml[1],
                                       (__nv_bfloat16*)wh1, (__nv_bfloat16*)wl1, HDIM * HDIM);
    prep_bias_kernel<<<HDIM / 256, 256>>>(bmu[1], bn[1], blv[1], ml[1], (float*)b1, HDIM);

    // layer 0: 128x128 tile, grid (16, 64) = 1024 CTAs
    gemm_split_bf16<4><<<dim3(HDIM / BN, BDIM / 128), NT, SMEM_M4>>>(
        (const __nv_bfloat16*)a0h, (const __nv_bfloat16*)a0l,
        (const __nv_bfloat16*)wh0, (const __nv_bfloat16*)wl0,
        (const float*)b0, DIN, HDIM, 1,
        (__nv_bfloat16*)a1h, (__nv_bfloat16*)a1l, nullptr);

    prep_weights_kernel<<<2048, 256>>>(wmu[2], wn[2], wlv[2], ml[2],
                                       (__nv_bfloat16*)wh2, (__nv_bfloat16*)wl2, DOUT * HDIM);
    prep_bias_kernel<<<DOUT / 256, 256>>>(bmu[2], bn[2], blv[2], ml[2], (float*)b2, DOUT);

    // layer 1: 128x128 tile, grid (16, 64)
    gemm_split_bf16<4><<<dim3(HDIM / BN, BDIM / 128), NT, SMEM_M4>>>(
        (const __nv_bfloat16*)a1h, (const __nv_bfloat16*)a1l,
        (const __nv_bfloat16*)wh1, (const __nv_bfloat16*)wl1,
        (const float*)b1, HDIM, HDIM, 1,
        (__nv_bfloat16*)a2h, (__nv_bfloat16*)a2l, nullptr);

    // layer 2 -> fp32 logits: 64x128 tile, grid (8, 128) = 1024 CTAs
    gemm_split_bf16<2><<<dim3(DOUT / BN, BDIM / 64), NT, SMEM_M2>>>(
        (const __nv_bfloat16*)a2h, (const __nv_bfloat16*)a2l,
        (const __nv_bfloat16*)wh2, (const __nv_bfloat16*)wl2,
        (const float*)b2, HDIM, DOUT, 0,
        nullptr, nullptr, (float*)d_out);

    // softmax in place
    softmax_kernel<<<BDIM, 256>>>((float*)d_out);
}

// round 13
// speedup vs baseline: 2.9722x; 1.0046x over previous
#include <cuda_runtime.h>
#include <cuda_bf16.h>
#include <cstdint>
#include <cstddef>

// ---------------------------------------------------------------------------
// Problem dims
// ---------------------------------------------------------------------------
#define BDIM   8192
#define DIN    2048
#define HDIM   2048
#define DOUT   1024
#define NCOMP  4

// ---------------------------------------------------------------------------
// Helpers (sm_103-safe)
// ---------------------------------------------------------------------------
__device__ __forceinline__ uint32_t smem_u32(const void* p) {
    uint32_t a;
    asm("{ .reg .u64 t; cvta.to.shared.u64 t, %1; cvt.u32.u64 %0, t; }"
        : "=r"(a) : "l"(p));
    return a;
}

#define SMEM_SWIZZLE_128B(o) ((o) ^ (((o) >> 3) & 0x70))

__device__ __forceinline__ void cp_async16(uint32_t dst, const void* src) {
    asm volatile("cp.async.cg.shared.global [%0], [%1], 16;"
                 :: "r"(dst), "l"(__cvta_generic_to_global(src)));
}
#define CP_COMMIT() asm volatile("cp.async.commit_group;" ::: "memory")
#define CP_WAIT(n)  asm volatile("cp.async.wait_group %0;" :: "n"(n) : "memory")

__device__ __forceinline__ void ldsm4(uint32_t* r, uint32_t addr) {
    asm volatile("ldmatrix.sync.aligned.m8n8.x4.shared.b16 {%0,%1,%2,%3}, [%4];"
                 : "=r"(r[0]), "=r"(r[1]), "=r"(r[2]), "=r"(r[3]) : "r"(addr));
}

__device__ __forceinline__ void mma16816(float* d, const uint32_t* a,
                                         uint32_t b0, uint32_t b1) {
    asm volatile(
        "mma.sync.aligned.m16n8k16.row.col.f32.bf16.bf16.f32 "
        "{%0,%1,%2,%3}, {%4,%5,%6,%7}, {%8,%9}, {%0,%1,%2,%3};"
        : "+f"(d[0]), "+f"(d[1]), "+f"(d[2]), "+f"(d[3])
        : "r"(a[0]), "r"(a[1]), "r"(a[2]), "r"(a[3]), "r"(b0), "r"(b1));
}

// ---------------------------------------------------------------------------
// Scratch buffers (__device__ globals; no cudaMalloc allowed)
// ---------------------------------------------------------------------------
__device__ __align__(16) __nv_bfloat16 g_wh0[HDIM * DIN];
__device__ __align__(16) __nv_bfloat16 g_wl0[HDIM * DIN];
__device__ __align__(16) __nv_bfloat16 g_wh1[HDIM * HDIM];
__device__ __align__(16) __nv_bfloat16 g_wl1[HDIM * HDIM];
__device__ __align__(16) __nv_bfloat16 g_wh2[DOUT * HDIM];
__device__ __align__(16) __nv_bfloat16 g_wl2[DOUT * HDIM];
__device__ __align__(16) float g_b0[HDIM];
__device__ __align__(16) float g_b1[HDIM];
__device__ __align__(16) float g_b2[DOUT];
__device__ __align__(16) __nv_bfloat16 g_a0h[BDIM * DIN];
__device__ __align__(16) __nv_bfloat16 g_a0l[BDIM * DIN];
__device__ __align__(16) __nv_bfloat16 g_a1h[BDIM * HDIM];
__device__ __align__(16) __nv_bfloat16 g_a1l[BDIM * HDIM];
__device__ __align__(16) __nv_bfloat16 g_a2h[BDIM * HDIM];
__device__ __align__(16) __nv_bfloat16 g_a2l[BDIM * HDIM];

// ---------------------------------------------------------------------------
// Prep kernels: fold mixture into effective bf16 hi/lo weights + fp32 bias
// ---------------------------------------------------------------------------
__device__ __forceinline__ void mix_coefs(const float* ml, const float* lv,
                                          float* cmu, float* cn) {
    float m[NCOMP], mx = -1e30f, s = 0.f, e[NCOMP];
    #pragma unroll
    for (int k = 0; k < NCOMP; k++) { m[k] = ml[k]; mx = fmaxf(mx, m[k]); }
    #pragma unroll
    for (int k = 0; k < NCOMP; k++) { e[k] = expf(m[k] - mx); s += e[k]; }
    #pragma unroll
    for (int k = 0; k < NCOMP; k++) {
        float w = e[k] / s;
        cmu[k] = w;
        cn[k]  = w * expf(0.5f * lv[k]);
    }
}

__device__ __forceinline__ void split_store(const float4 acc,
                                            __nv_bfloat16* whi,
                                            __nv_bfloat16* wlo, size_t i) {
    __nv_bfloat16 h0 = __float2bfloat16(acc.x);
    __nv_bfloat16 h1 = __float2bfloat16(acc.y);
    __nv_bfloat16 h2 = __float2bfloat16(acc.z);
    __nv_bfloat16 h3 = __float2bfloat16(acc.w);
    __nv_bfloat16 l0 = __float2bfloat16(acc.x - __bfloat162float(h0));
    __nv_bfloat16 l1 = __float2bfloat16(acc.y - __bfloat162float(h1));
    __nv_bfloat16 l2 = __float2bfloat16(acc.z - __bfloat162float(h2));
    __nv_bfloat16 l3 = __float2bfloat16(acc.w - __bfloat162float(h3));
    ((__nv_bfloat162*)whi)[2 * i]     = __halves2bfloat162(h0, h1);
    ((__nv_bfloat162*)whi)[2 * i + 1] = __halves2bfloat162(h2, h3);
    ((__nv_bfloat162*)wlo)[2 * i]     = __halves2bfloat162(l0, l1);
    ((__nv_bfloat162*)wlo)[2 * i + 1] = __halves2bfloat162(l2, l3);
}

__device__ __forceinline__ float4 mix4(const float4* wmu, const float4* wn,
                                       size_t n4, size_t i,
                                       const float* cmu, const float* cn) {
    float4 acc = make_float4(0.f, 0.f, 0.f, 0.f);
    #pragma unroll
    for (int k = 0; k < NCOMP; k++) {
        float4 a = wmu[(size_t)k * n4 + i];
        float4 b = wn[(size_t)k * n4 + i];
        acc.x += cmu[k] * a.x + cn[k] * b.x;
        acc.y += cmu[k] * a.y + cn[k] * b.y;
        acc.z += cmu[k] * a.z + cn[k] * b.z;
        acc.w += cmu[k] * a.w + cn[k] * b.w;
    }
    return acc;
}

// 2 float4 per thread per stream for deeper MLP
__global__ void prep_weights_kernel(const float* __restrict__ wmu,
                                    const float* __restrict__ wn,
                                    const float* __restrict__ wlv,
                                    const float* __restrict__ ml,
                                    __nv_bfloat16* __restrict__ whi,
                                    __nv_bfloat16* __restrict__ wlo,
                                    int n) {
    __shared__ float cmu[NCOMP], cn[NCOMP];
    if (threadIdx.x == 0) mix_coefs(ml, wlv, cmu, cn);
    __syncthreads();
    size_t n4 = (size_t)(n >> 2);
    size_t stride = (size_t)gridDim.x * blockDim.x;
    for (size_t i = (size_t)blockIdx.x * blockDim.x + threadIdx.x; i < n4;
         i += 2 * stride) {
        size_t j = i + stride;
        float4 a0 = mix4((const float4*)wmu, (const float4*)wn, n4, i, cmu, cn);
        if (j < n4) {
            float4 a1 = mix4((const float4*)wmu, (const float4*)wn, n4, j, cmu, cn);
            split_store(a0, whi, wlo, i);
            split_store(a1, whi, wlo, j);
        } else {
            split_store(a0, whi, wlo, i);
        }
    }
}

// one kernel for all 3 biases; segments are multiples of 256 so each block
// serves exactly one segment
__global__ void prep_bias_all_kernel(
    const float* __restrict__ bmu0, const float* __restrict__ bn0,
    const float* __restrict__ blv0, const float* __restrict__ ml0,
    const float* __restrict__ bmu1, const float* __restrict__ bn1,
    const float* __restrict__ blv1, const float* __restrict__ ml1,
    const float* __restrict__ bmu2, const float* __restrict__ bn2,
    const float* __restrict__ blv2, const float* __restrict__ ml2,
    float* __restrict__ b0, float* __restrict__ b1, float* __restrict__ b2) {
    __shared__ float cmu[NCOMP], cn[NCOMP];
    int g = blockIdx.x * blockDim.x + threadIdx.x;
    const float* bmu; const float* bn; const float* blv; const float* ml;
    float* out; int o; int O;
    if (g < HDIM)              { bmu = bmu0; bn = bn0; blv = blv0; ml = ml0; out = b0; o = g;               O = HDIM; }
    else if (g < 2 * HDIM)     { bmu = bmu1; bn = bn1; blv = blv1; ml = ml1; out = b1; o = g - HDIM;        O = HDIM; }
    else                       { bmu = bmu2; bn = bn2; blv = blv2; ml = ml2; out = b2; o = g - 2 * HDIM;    O = DOUT; }
    if (threadIdx.x == 0) mix_coefs(ml, blv, cmu, cn);
    __syncthreads();
    float e = 0.f;
    #pragma unroll
    for (int k = 0; k < NCOMP; k++)
        e += cmu[k] * bmu[k * O + o] + cn[k] * bn[k * O + o];
    out[o] = e;
}

__global__ void split_x_kernel(const float* __restrict__ x,
                               __nv_bfloat16* __restrict__ xh,
                               __nv_bfloat16* __restrict__ xl, int n) {
    size_t n4 = (size_t)(n >> 2);
    size_t stride = (size_t)gridDim.x * blockDim.x;
    for (size_t i = (size_t)blockIdx.x * blockDim.x + threadIdx.x; i < n4;
         i += 2 * stride) {
        size_t j = i + stride;
        float4 v0 = ((const float4*)x)[i];
        if (j < n4) {
            float4 v1 = ((const float4*)x)[j];
            split_store(v0, xh, xl, i);
            split_store(v1, xh, xl, j);
        } else {
            split_store(v0, xh, xl, i);
        }
    }
}

// ---------------------------------------------------------------------------
// mma.sync GEMM:  C[B,O] = A[B,I] @ W[O,I]^T + bias   (split bf16 hi/lo)
// EXACT R9/R12 pipeline: 2 cp.async stages, ONE __syncthreads per iter,
// static dual-buffer addressing. MFRAG=4 -> 128x128 (L0/L1), =2 -> 64x128 (L2).
// ---------------------------------------------------------------------------
#define BN 128
#define BK 64
#define NT 256

template <int MFRAG>
__global__ void __launch_bounds__(NT, 1)
gemm_split_bf16(const __nv_bfloat16* __restrict__ Ah,
                const __nv_bfloat16* __restrict__ Al,
                const __nv_bfloat16* __restrict__ Wh,
                const __nv_bfloat16* __restrict__ Wl,
                const float* __restrict__ bias,
                int Idim, int Odim, int relu_split,
                __nv_bfloat16* __restrict__ Oh,
                __nv_bfloat16* __restrict__ Ol,
                float* __restrict__ Of) {
    constexpr int BM = MFRAG * 32;
    constexpr int OFF_AL = BM * 128;
    constexpr int OFF_WH = 2 * BM * 128;
    constexpr int OFF_WL = 2 * BM * 128 + 16384;
    constexpr int STAGE  = 2 * BM * 128 + 32768;

    extern __shared__ char smem[];
    const uint32_t sb = smem_u32(smem);
    const int tid = threadIdx.x;
    const int wid = tid >> 5, l = tid & 31;
    const int n0 = blockIdx.x * BN, m0 = blockIdx.y * BM;
    const int wm = (wid >> 2) * (MFRAG * 16);
    const int wn = (wid & 3) * 32;
    const int lm = l >> 3, lr = l & 7;

    float acc[MFRAG][4][4];
    #pragma unroll
    for (int i = 0; i < MFRAG; i++)
        #pragma unroll
        for (int j = 0; j < 4; j++)
            #pragma unroll
            for (int q = 0; q < 4; q++) acc[i][j][q] = 0.f;

    const int nk = Idim / BK;

    auto issue = [&](int s, int k0) {
        uint32_t base = sb + s * STAGE;
        #pragma unroll
        for (int j = 0; j < MFRAG; j++) {
            int c = tid + j * NT;
            int row = c >> 3, col = c & 7;
            uint32_t so = SMEM_SWIZZLE_128B((uint32_t)(row * 128 + col * 16));
            size_t g = (size_t)(m0 + row) * Idim + k0 + col * 8;
            cp_async16(base + so, Ah + g);
            cp_async16(base + OFF_AL + so, Al + g);
        }
        #pragma unroll
        for (int j = 0; j < 4; j++) {
            int c = tid + j * NT;
            int row = c >> 3, col = c & 7;
            uint32_t so = SMEM_SWIZZLE_128B((uint32_t)(row * 128 + col * 16));
            size_t g = (size_t)(n0 + row) * Idim + k0 + col * 8;
            cp_async16(base + OFF_WH + so, Wh + g);
            cp_async16(base + OFF_WL + so, Wl + g);
        }
    };

    issue(0, 0);
    CP_COMMIT();

    for (int it = 0; it < nk; ++it) {
        CP_WAIT(0);
        __syncthreads();
        if (it + 1 < nk) {
            issue((it + 1) & 1, (it + 1) * BK);
            CP_COMMIT();
        }

        uint32_t bA = sb + (it & 1) * STAGE;
        #pragma unroll
        for (int kk = 0; kk < 4; kk++) {
            uint32_t ah[MFRAG][4], al[MFRAG][4];
            #pragma unroll
            for (int mf = 0; mf < MFRAG; mf++) {
                uint32_t off = SMEM_SWIZZLE_128B(
                    (uint32_t)((wm + mf * 16 + (lm & 1) * 8 + lr) * 128 +
                               (kk * 2 + (lm >> 1)) * 16));
                ldsm4(ah[mf], bA + off);
                ldsm4(al[mf], bA + OFF_AL + off);
            }
            #pragma unroll
            for (int nf2 = 0; nf2 < 2; nf2++) {
                uint32_t off = SMEM_SWIZZLE_128B(
                    (uint32_t)((wn + nf2 * 16 + (lm >> 1) * 8 + lr) * 128 +
                               (kk * 2 + (lm & 1)) * 16));
                uint32_t bh[4], bl[4];
                ldsm4(bh, bA + OFF_WH + off);
                ldsm4(bl, bA + OFF_WL + off);
                #pragma unroll
                for (int mf = 0; mf < MFRAG; mf++) {
                    mma16816(acc[mf][2 * nf2],     ah[mf], bh[0], bh[1]);
                    mma16816(acc[mf][2 * nf2 + 1], ah[mf], bh[2], bh[3]);
                }
                #pragma unroll
                for (int mf = 0; mf < MFRAG; mf++) {
                    mma16816(acc[mf][2 * nf2],     ah[mf], bl[0], bl[1]);
                    mma16816(acc[mf][2 * nf2 + 1], ah[mf], bl[2], bl[3]);
                }
                #pragma unroll
                for (int mf = 0; mf < MFRAG; mf++) {
                    mma16816(acc[mf][2 * nf2],     al[mf], bh[0], bh[1]);
                    mma16816(acc[mf][2 * nf2 + 1], al[mf], bh[2], bh[3]);
                }
            }
        }
    }

    // Epilogue
    const int cb = n0 + wn;
    if (relu_split) {
        #pragma unroll
        for (int mf = 0; mf < MFRAG; mf++) {
            int r0 = m0 + wm + mf * 16 + (l >> 2);
            #pragma unroll
            for (int nf = 0; nf < 4; nf++) {
                int col = cb + nf * 8 + 2 * (l & 3);
                float2 bv = *(const float2*)(bias + col);
                float v0 = fmaxf(acc[mf][nf][0] + bv.x, 0.f);
                float v1 = fmaxf(acc[mf][nf][1] + bv.y, 0.f);
                float v2 = fmaxf(acc[mf][nf][2] + bv.x, 0.f);
                float v3 = fmaxf(acc[mf][nf][3] + bv.y, 0.f);
                __nv_bfloat16 h0 = __float2bfloat16(v0);
                __nv_bfloat16 h1 = __float2bfloat16(v1);
                __nv_bfloat16 h2 = __float2bfloat16(v2);
                __nv_bfloat16 h3 = __float2bfloat16(v3);
                __nv_bfloat16 q0 = __float2bfloat16(v0 - __bfloat162float(h0));
                __nv_bfloat16 q1 = __float2bfloat16(v1 - __bfloat162float(h1));
                __nv_bfloat16 q2 = __float2bfloat16(v2 - __bfloat162float(h2));
                __nv_bfloat16 q3 = __float2bfloat16(v3 - __bfloat162float(h3));
                *(__nv_bfloat162*)(Oh + (size_t)r0 * Odim + col) = __halves2bfloat162(h0, h1);
                *(__nv_bfloat162*)(Oh + (size_t)(r0 + 8) * Odim + col) = __halves2bfloat162(h2, h3);
                *(__nv_bfloat162*)(Ol + (size_t)r0 * Odim + col) = __halves2bfloat162(q0, q1);
                *(__nv_bfloat162*)(Ol + (size_t)(r0 + 8) * Odim + col) = __halves2bfloat162(q2, q3);
            }
        }
    } else {
        #pragma unroll
        for (int mf = 0; mf < MFRAG; mf++) {
            int r0 = m0 + wm + mf * 16 + (l >> 2);
            #pragma unroll
            for (int nf = 0; nf < 4; nf++) {
                int col = cb + nf * 8 + 2 * (l & 3);
                float2 bv = *(const float2*)(bias + col);
                float2 o0 = make_float2(acc[mf][nf][0] + bv.x, acc[mf][nf][1] + bv.y);
                float2 o1 = make_float2(acc[mf][nf][2] + bv.x, acc[mf][nf][3] + bv.y);
                *(float2*)(Of + (size_t)r0 * Odim + col) = o0;
                *(float2*)(Of + (size_t)(r0 + 8) * Odim + col) = o1;
            }
        }
    }
}

#define SMEM_M4 (2 * (2 * 128 * 128 + 32768))   // 128 KB
#define SMEM_M2 (2 * (2 * 64 * 128 + 32768))    // 96 KB

// ---------------------------------------------------------------------------
// Row softmax (in-place), 1024 cols, 256 threads/row, float4 I/O
// ---------------------------------------------------------------------------
__global__ void softmax_kernel(float* __restrict__ io) {
    __shared__ float red[8];
    int b = blockIdx.x;
    float* row = io + (size_t)b * DOUT;
    int t = threadIdx.x;
    float4 v = ((const float4*)row)[t];
    float m = fmaxf(fmaxf(v.x, v.y), fmaxf(v.z, v.w));
    #pragma unroll
    for (int o = 16; o; o >>= 1) m = fmaxf(m, __shfl_xor_sync(0xffffffffu, m, o));
    if ((t & 31) == 0) red[t >> 5] = m;
    __syncthreads();
    m = red[0];
    #pragma unroll
    for (int w = 1; w < 8; w++) m = fmaxf(m, red[w]);
    v.x = expf(v.x - m); v.y = expf(v.y - m);
    v.z = expf(v.z - m); v.w = expf(v.w - m);
    float s = v.x + v.y + v.z + v.w;
    #pragma unroll
    for (int o = 16; o; o >>= 1) s += __shfl_xor_sync(0xffffffffu, s, o);
    __syncthreads();
    if ((t & 31) == 0) red[t >> 5] = s;
    __syncthreads();
    s = red[0];
    #pragma unroll
    for (int w = 1; w < 8; w++) s += red[w];
    float inv = 1.0f / s;
    v.x *= inv; v.y *= inv; v.z *= inv; v.w *= inv;
    ((float4*)row)[t] = v;
}

// ---------------------------------------------------------------------------
// Launcher
// ---------------------------------------------------------------------------
extern "C" void kernel_launch(void* const* d_in, const int* in_sizes, int n_in,
                              void* d_out, int out_size) {
    (void)in_sizes; (void)n_in; (void)out_size;
    const float* x   = (const float*)d_in[0];
    const float* wmu[3] = {(const float*)d_in[1],  (const float*)d_in[8],  (const float*)d_in[15]};
    const float* bmu[3] = {(const float*)d_in[2],  (const float*)d_in[9],  (const float*)d_in[16]};
    const float* wlv[3] = {(const float*)d_in[3],  (const float*)d_in[10], (const float*)d_in[17]};
    const float* blv[3] = {(const float*)d_in[4],  (const float*)d_in[11], (const float*)d_in[18]};
    const float* ml[3]  = {(const float*)d_in[5],  (const float*)d_in[12], (const float*)d_in[19]};
    const float* wn[3]  = {(const float*)d_in[6],  (const float*)d_in[13], (const float*)d_in[20]};
    const float* bn[3]  = {(const float*)d_in[7],  (const float*)d_in[14], (const float*)d_in[21]};

    void *wh0, *wl0, *wh1, *wl1, *wh2, *wl2, *b0, *b1, *b2;
    void *a0h, *a0l, *a1h, *a1l, *a2h, *a2l;
    cudaGetSymbolAddress(&wh0, g_wh0); cudaGetSymbolAddress(&wl0, g_wl0);
    cudaGetSymbolAddress(&wh1, g_wh1); cudaGetSymbolAddress(&wl1, g_wl1);
    cudaGetSymbolAddress(&wh2, g_wh2); cudaGetSymbolAddress(&wl2, g_wl2);
    cudaGetSymbolAddress(&b0, g_b0);   cudaGetSymbolAddress(&b1, g_b1);
    cudaGetSymbolAddress(&b2, g_b2);
    cudaGetSymbolAddress(&a0h, g_a0h); cudaGetSymbolAddress(&a0l, g_a0l);
    cudaGetSymbolAddress(&a1h, g_a1h); cudaGetSymbolAddress(&a1l, g_a1l);
    cudaGetSymbolAddress(&a2h, g_a2h); cudaGetSymbolAddress(&a2l, g_a2l);

    cudaFuncSetAttribute(gemm_split_bf16<4>,
                         cudaFuncAttributeMaxDynamicSharedMemorySize, SMEM_M4);
    cudaFuncSetAttribute(gemm_split_bf16<2>,
                         cudaFuncAttributeMaxDynamicSharedMemorySize, SMEM_M2);

    // prep
    prep_weights_kernel<<<1024, 256>>>(wmu[0], wn[0], wlv[0], ml[0],
                                       (__nv_bfloat16*)wh0, (__nv_bfloat16*)wl0, HDIM * DIN);
    split_x_kernel<<<1024, 256>>>(x, (__nv_bfloat16*)a0h, (__nv_bfloat16*)a0l, BDIM * DIN);
    prep_bias_all_kernel<<<(2 * HDIM + DOUT) / 256, 256>>>(
        bmu[0], bn[0], blv[0], ml[0],
        bmu[1], bn[1], blv[1], ml[1],
        bmu[2], bn[2], blv[2], ml[2],
        (float*)b0, (float*)b1, (float*)b2);
    prep_weights_kernel<<<1024, 256>>>(wmu[1], wn[1], wlv[1], ml[1],
                                       (__nv_bfloat16*)wh1, (__nv_bfloat16*)wl1, HDIM * HDIM);

    // layer 0: 128x128 tile, grid (16, 64) = 1024 CTAs
    gemm_split_bf16<4><<<dim3(HDIM / BN, BDIM / 128), NT, SMEM_M4>>>(
        (const __nv_bfloat16*)a0h, (const __nv_bfloat16*)a0l,
        (const __nv_bfloat16*)wh0, (const __nv_bfloat16*)wl0,
        (const float*)b0, DIN, HDIM, 1,
        (__nv_bfloat16*)a1h, (__nv_bfloat16*)a1l, nullptr);

    prep_weights_kernel<<<1024, 256>>>(wmu[2], wn[2], wlv[2], ml[2],
                                       (__nv_bfloat16*)wh2, (__nv_bfloat16*)wl2, DOUT * HDIM);

    // layer 1: 128x128 tile, grid (16, 64)
    gemm_split_bf16<4><<<dim3(HDIM / BN, BDIM / 128), NT, SMEM_M4>>>(
        (const __nv_bfloat16*)a1h, (const __nv_bfloat16*)a1l,
        (const __nv_bfloat16*)wh1, (const __nv_bfloat16*)wl1,
        (const float*)b1, HDIM, HDIM, 1,
        (__nv_bfloat16*)a2h, (__nv_bfloat16*)a2l, nullptr);

    // layer 2 -> fp32 logits: 64x128 tile, grid (8, 128) = 1024 CTAs
    gemm_split_bf16<2><<<dim3(DOUT / BN, BDIM / 64), NT, SMEM_M2>>>(
        (const __nv_bfloat16*)a2h, (const __nv_bfloat16*)a2l,
        (const __nv_bfloat16*)wh2, (const __nv_bfloat16*)wl2,
        (const float*)b2, HDIM, DOUT, 0,
        nullptr, nullptr, (float*)d_out);

    // softmax in place
    softmax_kernel<<<BDIM, 256>>>((float*)d_out);
}

// round 14
// speedup vs baseline: 2.9985x; 1.0088x over previous
#include <cuda_runtime.h>
#include <cuda_bf16.h>
#include <cstdint>
#include <cstddef>

// ---------------------------------------------------------------------------
// Problem dims
// ---------------------------------------------------------------------------
#define BDIM   8192
#define DIN    2048
#define HDIM   2048
#define DOUT   1024
#define NCOMP  4

// ---------------------------------------------------------------------------
// Helpers (sm_103-safe)
// ---------------------------------------------------------------------------
__device__ __forceinline__ uint32_t smem_u32(const void* p) {
    uint32_t a;
    asm("{ .reg .u64 t; cvta.to.shared.u64 t, %1; cvt.u32.u64 %0, t; }"
        : "=r"(a) : "l"(p));
    return a;
}

#define SMEM_SWIZZLE_128B(o) ((o) ^ (((o) >> 3) & 0x70))

__device__ __forceinline__ void cp_async16(uint32_t dst, const void* src) {
    asm volatile("cp.async.cg.shared.global [%0], [%1], 16;"
                 :: "r"(dst), "l"(__cvta_generic_to_global(src)));
}
#define CP_COMMIT() asm volatile("cp.async.commit_group;" ::: "memory")
#define CP_WAIT(n)  asm volatile("cp.async.wait_group %0;" :: "n"(n) : "memory")

__device__ __forceinline__ void ldsm4(uint32_t* r, uint32_t addr) {
    asm volatile("ldmatrix.sync.aligned.m8n8.x4.shared.b16 {%0,%1,%2,%3}, [%4];"
                 : "=r"(r[0]), "=r"(r[1]), "=r"(r[2]), "=r"(r[3]) : "r"(addr));
}

__device__ __forceinline__ void mma16816(float* d, const uint32_t* a,
                                         uint32_t b0, uint32_t b1) {
    asm volatile(
        "mma.sync.aligned.m16n8k16.row.col.f32.bf16.bf16.f32 "
        "{%0,%1,%2,%3}, {%4,%5,%6,%7}, {%8,%9}, {%0,%1,%2,%3};"
        : "+f"(d[0]), "+f"(d[1]), "+f"(d[2]), "+f"(d[3])
        : "r"(a[0]), "r"(a[1]), "r"(a[2]), "r"(a[3]), "r"(b0), "r"(b1));
}

// ---------------------------------------------------------------------------
// Scratch buffers (__device__ globals; no cudaMalloc allowed)
// ---------------------------------------------------------------------------
__device__ __align__(16) __nv_bfloat16 g_wh0[HDIM * DIN];
__device__ __align__(16) __nv_bfloat16 g_wl0[HDIM * DIN];
__device__ __align__(16) __nv_bfloat16 g_wh1[HDIM * HDIM];
__device__ __align__(16) __nv_bfloat16 g_wl1[HDIM * HDIM];
__device__ __align__(16) __nv_bfloat16 g_wh2[DOUT * HDIM];
__device__ __align__(16) __nv_bfloat16 g_wl2[DOUT * HDIM];
__device__ __align__(16) float g_b0[HDIM];
__device__ __align__(16) float g_b1[HDIM];
__device__ __align__(16) float g_b2[DOUT];
__device__ __align__(16) __nv_bfloat16 g_a0h[BDIM * DIN];
__device__ __align__(16) __nv_bfloat16 g_a0l[BDIM * DIN];
__device__ __align__(16) __nv_bfloat16 g_a1h[BDIM * HDIM];
__device__ __align__(16) __nv_bfloat16 g_a1l[BDIM * HDIM];
__device__ __align__(16) __nv_bfloat16 g_a2h[BDIM * HDIM];
__device__ __align__(16) __nv_bfloat16 g_a2l[BDIM * HDIM];

// ---------------------------------------------------------------------------
// Prep: fold mixture into effective bf16 hi/lo weights + fp32 bias
// ---------------------------------------------------------------------------
__device__ __forceinline__ void mix_coefs(const float* ml, const float* lv,
                                          float* cmu, float* cn) {
    float m[NCOMP], mx = -1e30f, s = 0.f, e[NCOMP];
    #pragma unroll
    for (int k = 0; k < NCOMP; k++) { m[k] = ml[k]; mx = fmaxf(mx, m[k]); }
    #pragma unroll
    for (int k = 0; k < NCOMP; k++) { e[k] = expf(m[k] - mx); s += e[k]; }
    #pragma unroll
    for (int k = 0; k < NCOMP; k++) {
        float w = e[k] / s;
        cmu[k] = w;
        cn[k]  = w * expf(0.5f * lv[k]);
    }
}

__device__ __forceinline__ void split_store(const float4 acc,
                                            __nv_bfloat16* whi,
                                            __nv_bfloat16* wlo, size_t i) {
    __nv_bfloat16 h0 = __float2bfloat16(acc.x);
    __nv_bfloat16 h1 = __float2bfloat16(acc.y);
    __nv_bfloat16 h2 = __float2bfloat16(acc.z);
    __nv_bfloat16 h3 = __float2bfloat16(acc.w);
    __nv_bfloat16 l0 = __float2bfloat16(acc.x - __bfloat162float(h0));
    __nv_bfloat16 l1 = __float2bfloat16(acc.y - __bfloat162float(h1));
    __nv_bfloat16 l2 = __float2bfloat16(acc.z - __bfloat162float(h2));
    __nv_bfloat16 l3 = __float2bfloat16(acc.w - __bfloat162float(h3));
    ((__nv_bfloat162*)whi)[2 * i]     = __halves2bfloat162(h0, h1);
    ((__nv_bfloat162*)whi)[2 * i + 1] = __halves2bfloat162(h2, h3);
    ((__nv_bfloat162*)wlo)[2 * i]     = __halves2bfloat162(l0, l1);
    ((__nv_bfloat162*)wlo)[2 * i + 1] = __halves2bfloat162(l2, l3);
}

__device__ __forceinline__ float4 mix4(const float4* wmu, const float4* wn,
                                       size_t n4, size_t i,
                                       const float* cmu, const float* cn) {
    float4 acc = make_float4(0.f, 0.f, 0.f, 0.f);
    #pragma unroll
    for (int k = 0; k < NCOMP; k++) {
        float4 a = wmu[(size_t)k * n4 + i];
        float4 b = wn[(size_t)k * n4 + i];
        acc.x += cmu[k] * a.x + cn[k] * b.x;
        acc.y += cmu[k] * a.y + cn[k] * b.y;
        acc.z += cmu[k] * a.z + cn[k] * b.z;
        acc.w += cmu[k] * a.w + cn[k] * b.w;
    }
    return acc;
}

// All 3 layers in one launch. Segment boundaries (in float4 units):
//   L0: 1M (4096 blocks), L1: 1M (4096 blocks), L2: 0.5M (2048 blocks).
// Each block lies entirely within one segment.
#define L0_F4 ((size_t)(HDIM) * DIN / 4)    // 1M
#define L1_F4 ((size_t)(HDIM) * HDIM / 4)   // 1M
#define L2_F4 ((size_t)(DOUT) * HDIM / 4)   // 0.5M
#define PREP_BLOCKS ((int)((L0_F4 + L1_F4 + L2_F4) / 256))

__global__ void prep_weights_all_kernel(
    const float* __restrict__ wmu0, const float* __restrict__ wn0,
    const float* __restrict__ wlv0, const float* __restrict__ ml0,
    const float* __restrict__ wmu1, const float* __restrict__ wn1,
    const float* __restrict__ wlv1, const float* __restrict__ ml1,
    const float* __restrict__ wmu2, const float* __restrict__ wn2,
    const float* __restrict__ wlv2, const float* __restrict__ ml2,
    __nv_bfloat16* __restrict__ wh0, __nv_bfloat16* __restrict__ wl0,
    __nv_bfloat16* __restrict__ wh1, __nv_bfloat16* __restrict__ wl1,
    __nv_bfloat16* __restrict__ wh2, __nv_bfloat16* __restrict__ wl2) {
    __shared__ float cmu[NCOMP], cn[NCOMP];
    size_t g = (size_t)blockIdx.x * blockDim.x;  // block-aligned base
    const float4* wmu; const float4* wn; const float* wlv; const float* ml;
    __nv_bfloat16* wh; __nv_bfloat16* wl; size_t n4; size_t base;
    if (g < L0_F4) {
        wmu = (const float4*)wmu0; wn = (const float4*)wn0;
        wlv = wlv0; ml = ml0; wh = wh0; wl = wl0; n4 = L0_F4; base = g;
    } else if (g < L0_F4 + L1_F4) {
        wmu = (const float4*)wmu1; wn = (const float4*)wn1;
        wlv = wlv1; ml = ml1; wh = wh1; wl = wl1; n4 = L1_F4; base = g - L0_F4;
    } else {
        wmu = (const float4*)wmu2; wn = (const float4*)wn2;
        wlv = wlv2; ml = ml2; wh = wh2; wl = wl2; n4 = L2_F4;
        base = g - L0_F4 - L1_F4;
    }
    if (threadIdx.x == 0) mix_coefs(ml, wlv, cmu, cn);
    __syncthreads();
    size_t i = base + threadIdx.x;
    float4 acc = mix4(wmu, wn, n4, i, cmu, cn);
    split_store(acc, wh, wl, i);
}

// one kernel for all 3 biases
__global__ void prep_bias_all_kernel(
    const float* __restrict__ bmu0, const float* __restrict__ bn0,
    const float* __restrict__ blv0, const float* __restrict__ ml0,
    const float* __restrict__ bmu1, const float* __restrict__ bn1,
    const float* __restrict__ blv1, const float* __restrict__ ml1,
    const float* __restrict__ bmu2, const float* __restrict__ bn2,
    const float* __restrict__ blv2, const float* __restrict__ ml2,
    float* __restrict__ b0, float* __restrict__ b1, float* __restrict__ b2) {
    __shared__ float cmu[NCOMP], cn[NCOMP];
    int g = blockIdx.x * blockDim.x + threadIdx.x;
    const float* bmu; const float* bn; const float* blv; const float* ml;
    float* out; int o; int O;
    if (g < HDIM)          { bmu = bmu0; bn = bn0; blv = blv0; ml = ml0; out = b0; o = g;            O = HDIM; }
    else if (g < 2 * HDIM) { bmu = bmu1; bn = bn1; blv = blv1; ml = ml1; out = b1; o = g - HDIM;     O = HDIM; }
    else                   { bmu = bmu2; bn = bn2; blv = blv2; ml = ml2; out = b2; o = g - 2 * HDIM; O = DOUT; }
    if (threadIdx.x == 0) mix_coefs(ml, blv, cmu, cn);
    __syncthreads();
    float e = 0.f;
    #pragma unroll
    for (int k = 0; k < NCOMP; k++)
        e += cmu[k] * bmu[k * O + o] + cn[k] * bn[k * O + o];
    out[o] = e;
}

__global__ void split_x_kernel(const float* __restrict__ x,
                               __nv_bfloat16* __restrict__ xh,
                               __nv_bfloat16* __restrict__ xl, int n) {
    size_t n4 = (size_t)(n >> 2);
    size_t stride = (size_t)gridDim.x * blockDim.x;
    for (size_t i = (size_t)blockIdx.x * blockDim.x + threadIdx.x; i < n4;
         i += 2 * stride) {
        size_t j = i + stride;
        float4 v0 = ((const float4*)x)[i];
        if (j < n4) {
            float4 v1 = ((const float4*)x)[j];
            split_store(v0, xh, xl, i);
            split_store(v1, xh, xl, j);
        } else {
            split_store(v0, xh, xl, i);
        }
    }
}

// ---------------------------------------------------------------------------
// mma.sync GEMM:  C[B,O] = A[B,I] @ W[O,I]^T + bias   (split bf16 hi/lo)
// PROVEN R9/R12/R13 pipeline: 2 cp.async stages, ONE __syncthreads per iter,
// static dual-buffer addressing. MFRAG=4 -> 128x128 (L0/L1), =2 -> 64x128 (L2).
// ---------------------------------------------------------------------------
#define BN 128
#define BK 64
#define NT 256

template <int MFRAG>
__global__ void __launch_bounds__(NT, 1)
gemm_split_bf16(const __nv_bfloat16* __restrict__ Ah,
                const __nv_bfloat16* __restrict__ Al,
                const __nv_bfloat16* __restrict__ Wh,
                const __nv_bfloat16* __restrict__ Wl,
                const float* __restrict__ bias,
                int Idim, int Odim, int relu_split,
                __nv_bfloat16* __restrict__ Oh,
                __nv_bfloat16* __restrict__ Ol,
                float* __restrict__ Of) {
    constexpr int BM = MFRAG * 32;
    constexpr int OFF_AL = BM * 128;
    constexpr int OFF_WH = 2 * BM * 128;
    constexpr int OFF_WL = 2 * BM * 128 + 16384;
    constexpr int STAGE  = 2 * BM * 128 + 32768;

    extern __shared__ char smem[];
    const uint32_t sb = smem_u32(smem);
    const int tid = threadIdx.x;
    const int wid = tid >> 5, l = tid & 31;
    const int n0 = blockIdx.x * BN, m0 = blockIdx.y * BM;
    const int wm = (wid >> 2) * (MFRAG * 16);
    const int wn = (wid & 3) * 32;
    const int lm = l >> 3, lr = l & 7;

    float acc[MFRAG][4][4];
    #pragma unroll
    for (int i = 0; i < MFRAG; i++)
        #pragma unroll
        for (int j = 0; j < 4; j++)
            #pragma unroll
            for (int q = 0; q < 4; q++) acc[i][j][q] = 0.f;

    const int nk = Idim / BK;

    auto issue = [&](int s, int k0) {
        uint32_t base = sb + s * STAGE;
        #pragma unroll
        for (int j = 0; j < MFRAG; j++) {
            int c = tid + j * NT;
            int row = c >> 3, col = c & 7;
            uint32_t so = SMEM_SWIZZLE_128B((uint32_t)(row * 128 + col * 16));
            size_t g = (size_t)(m0 + row) * Idim + k0 + col * 8;
            cp_async16(base + so, Ah + g);
            cp_async16(base + OFF_AL + so, Al + g);
        }
        #pragma unroll
        for (int j = 0; j < 4; j++) {
            int c = tid + j * NT;
            int row = c >> 3, col = c & 7;
            uint32_t so = SMEM_SWIZZLE_128B((uint32_t)(row * 128 + col * 16));
            size_t g = (size_t)(n0 + row) * Idim + k0 + col * 8;
            cp_async16(base + OFF_WH + so, Wh + g);
            cp_async16(base + OFF_WL + so, Wl + g);
        }
    };

    issue(0, 0);
    CP_COMMIT();

    for (int it = 0; it < nk; ++it) {
        CP_WAIT(0);
        __syncthreads();
        if (it + 1 < nk) {
            issue((it + 1) & 1, (it + 1) * BK);
            CP_COMMIT();
        }

        uint32_t bA = sb + (it & 1) * STAGE;
        #pragma unroll
        for (int kk = 0; kk < 4; kk++) {
            uint32_t ah[MFRAG][4], al[MFRAG][4];
            #pragma unroll
            for (int mf = 0; mf < MFRAG; mf++) {
                uint32_t off = SMEM_SWIZZLE_128B(
                    (uint32_t)((wm + mf * 16 + (lm & 1) * 8 + lr) * 128 +
                               (kk * 2 + (lm >> 1)) * 16));
                ldsm4(ah[mf], bA + off);
                ldsm4(al[mf], bA + OFF_AL + off);
            }
            #pragma unroll
            for (int nf2 = 0; nf2 < 2; nf2++) {
                uint32_t off = SMEM_SWIZZLE_128B(
                    (uint32_t)((wn + nf2 * 16 + (lm >> 1) * 8 + lr) * 128 +
                               (kk * 2 + (lm & 1)) * 16));
                uint32_t bh[4], bl[4];
                ldsm4(bh, bA + OFF_WH + off);
                ldsm4(bl, bA + OFF_WL + off);
                #pragma unroll
                for (int mf = 0; mf < MFRAG; mf++) {
                    mma16816(acc[mf][2 * nf2],     ah[mf], bh[0], bh[1]);
                    mma16816(acc[mf][2 * nf2 + 1], ah[mf], bh[2], bh[3]);
                }
                #pragma unroll
                for (int mf = 0; mf < MFRAG; mf++) {
                    mma16816(acc[mf][2 * nf2],     ah[mf], bl[0], bl[1]);
                    mma16816(acc[mf][2 * nf2 + 1], ah[mf], bl[2], bl[3]);
                }
                #pragma unroll
                for (int mf = 0; mf < MFRAG; mf++) {
                    mma16816(acc[mf][2 * nf2],     al[mf], bh[0], bh[1]);
                    mma16816(acc[mf][2 * nf2 + 1], al[mf], bh[2], bh[3]);
                }
            }
        }
    }

    // Epilogue
    const int cb = n0 + wn;
    if (relu_split) {
        #pragma unroll
        for (int mf = 0; mf < MFRAG; mf++) {
            int r0 = m0 + wm + mf * 16 + (l >> 2);
            #pragma unroll
            for (int nf = 0; nf < 4; nf++) {
                int col = cb + nf * 8 + 2 * (l & 3);
                float2 bv = *(const float2*)(bias + col);
                float v0 = fmaxf(acc[mf][nf][0] + bv.x, 0.f);
                float v1 = fmaxf(acc[mf][nf][1] + bv.y, 0.f);
                float v2 = fmaxf(acc[mf][nf][2] + bv.x, 0.f);
                float v3 = fmaxf(acc[mf][nf][3] + bv.y, 0.f);
                __nv_bfloat16 h0 = __float2bfloat16(v0);
                __nv_bfloat16 h1 = __float2bfloat16(v1);
                __nv_bfloat16 h2 = __float2bfloat16(v2);
                __nv_bfloat16 h3 = __float2bfloat16(v3);
                __nv_bfloat16 q0 = __float2bfloat16(v0 - __bfloat162float(h0));
                __nv_bfloat16 q1 = __float2bfloat16(v1 - __bfloat162float(h1));
                __nv_bfloat16 q2 = __float2bfloat16(v2 - __bfloat162float(h2));
                __nv_bfloat16 q3 = __float2bfloat16(v3 - __bfloat162float(h3));
                *(__nv_bfloat162*)(Oh + (size_t)r0 * Odim + col) = __halves2bfloat162(h0, h1);
                *(__nv_bfloat162*)(Oh + (size_t)(r0 + 8) * Odim + col) = __halves2bfloat162(h2, h3);
                *(__nv_bfloat162*)(Ol + (size_t)r0 * Odim + col) = __halves2bfloat162(q0, q1);
                *(__nv_bfloat162*)(Ol + (size_t)(r0 + 8) * Odim + col) = __halves2bfloat162(q2, q3);
            }
        }
    } else {
        #pragma unroll
        for (int mf = 0; mf < MFRAG; mf++) {
            int r0 = m0 + wm + mf * 16 + (l >> 2);
            #pragma unroll
            for (int nf = 0; nf < 4; nf++) {
                int col = cb + nf * 8 + 2 * (l & 3);
                float2 bv = *(const float2*)(bias + col);
                float2 o0 = make_float2(acc[mf][nf][0] + bv.x, acc[mf][nf][1] + bv.y);
                float2 o1 = make_float2(acc[mf][nf][2] + bv.x, acc[mf][nf][3] + bv.y);
                *(float2*)(Of + (size_t)r0 * Odim + col) = o0;
                *(float2*)(Of + (size_t)(r0 + 8) * Odim + col) = o1;
            }
        }
    }
}

#define SMEM_M4 (2 * (2 * 128 * 128 + 32768))   // 128 KB
#define SMEM_M2 (2 * (2 * 64 * 128 + 32768))    // 96 KB

// ---------------------------------------------------------------------------
// Row softmax (in-place), 1024 cols, 256 threads/row, float4 I/O
// ---------------------------------------------------------------------------
__global__ void softmax_kernel(float* __restrict__ io) {
    __shared__ float red[8];
    int b = blockIdx.x;
    float* row = io + (size_t)b * DOUT;
    int t = threadIdx.x;
    float4 v = ((const float4*)row)[t];
    float m = fmaxf(fmaxf(v.x, v.y), fmaxf(v.z, v.w));
    #pragma unroll
    for (int o = 16; o; o >>= 1) m = fmaxf(m, __shfl_xor_sync(0xffffffffu, m, o));
    if ((t & 31) == 0) red[t >> 5] = m;
    __syncthreads();
    m = red[0];
    #pragma unroll
    for (int w = 1; w < 8; w++) m = fmaxf(m, red[w]);
    v.x = expf(v.x - m); v.y = expf(v.y - m);
    v.z = expf(v.z - m); v.w = expf(v.w - m);
    float s = v.x + v.y + v.z + v.w;
    #pragma unroll
    for (int o = 16; o; o >>= 1) s += __shfl_xor_sync(0xffffffffu, s, o);
    __syncthreads();
    if ((t & 31) == 0) red[t >> 5] = s;
    __syncthreads();
    s = red[0];
    #pragma unroll
    for (int w = 1; w < 8; w++) s += red[w];
    float inv = 1.0f / s;
    v.x *= inv; v.y *= inv; v.z *= inv; v.w *= inv;
    ((float4*)row)[t] = v;
}

// ---------------------------------------------------------------------------
// Launcher
// ---------------------------------------------------------------------------
extern "C" void kernel_launch(void* const* d_in, const int* in_sizes, int n_in,
                              void* d_out, int out_size) {
    (void)in_sizes; (void)n_in; (void)out_size;
    const float* x   = (const float*)d_in[0];
    const float* wmu[3] = {(const float*)d_in[1],  (const float*)d_in[8],  (const float*)d_in[15]};
    const float* bmu[3] = {(const float*)d_in[2],  (const float*)d_in[9],  (const float*)d_in[16]};
    const float* wlv[3] = {(const float*)d_in[3],  (const float*)d_in[10], (const float*)d_in[17]};
    const float* blv[3] = {(const float*)d_in[4],  (const float*)d_in[11], (const float*)d_in[18]};
    const float* ml[3]  = {(const float*)d_in[5],  (const float*)d_in[12], (const float*)d_in[19]};
    const float* wn[3]  = {(const float*)d_in[6],  (const float*)d_in[13], (const float*)d_in[20]};
    const float* bn[3]  = {(const float*)d_in[7],  (const float*)d_in[14], (const float*)d_in[21]};

    void *wh0, *wl0, *wh1, *wl1, *wh2, *wl2, *b0, *b1, *b2;
    void *a0h, *a0l, *a1h, *a1l, *a2h, *a2l;
    cudaGetSymbolAddress(&wh0, g_wh0); cudaGetSymbolAddress(&wl0, g_wl0);
    cudaGetSymbolAddress(&wh1, g_wh1); cudaGetSymbolAddress(&wl1, g_wl1);
    cudaGetSymbolAddress(&wh2, g_wh2); cudaGetSymbolAddress(&wl2, g_wl2);
    cudaGetSymbolAddress(&b0, g_b0);   cudaGetSymbolAddress(&b1, g_b1);
    cudaGetSymbolAddress(&b2, g_b2);
    cudaGetSymbolAddress(&a0h, g_a0h); cudaGetSymbolAddress(&a0l, g_a0l);
    cudaGetSymbolAddress(&a1h, g_a1h); cudaGetSymbolAddress(&a1l, g_a1l);
    cudaGetSymbolAddress(&a2h, g_a2h); cudaGetSymbolAddress(&a2l, g_a2l);

    cudaFuncSetAttribute(gemm_split_bf16<4>,
                         cudaFuncAttributeMaxDynamicSharedMemorySize, SMEM_M4);
    cudaFuncSetAttribute(gemm_split_bf16<2>,
                         cudaFuncAttributeMaxDynamicSharedMemorySize, SMEM_M2);

    // prep: input split, all weights (one launch), all biases (one launch)
    split_x_kernel<<<1024, 256>>>(x, (__nv_bfloat16*)a0h, (__nv_bfloat16*)a0l, BDIM * DIN);
    prep_weights_all_kernel<<<PREP_BLOCKS, 256>>>(
        wmu[0], wn[0], wlv[0], ml[0],
        wmu[1], wn[1], wlv[1], ml[1],
        wmu[2], wn[2], wlv[2], ml[2],
        (__nv_bfloat16*)wh0, (__nv_bfloat16*)wl0,
        (__nv_bfloat16*)wh1, (__nv_bfloat16*)wl1,
        (__nv_bfloat16*)wh2, (__nv_bfloat16*)wl2);
    prep_bias_all_kernel<<<(2 * HDIM + DOUT) / 256, 256>>>(
        bmu[0], bn[0], blv[0], ml[0],
        bmu[1], bn[1], blv[1], ml[1],
        bmu[2], bn[2], blv[2], ml[2],
        (float*)b0, (float*)b1, (float*)b2);

    // layer 0: 128x128 tile, grid (16, 64) = 1024 CTAs
    gemm_split_bf16<4><<<dim3(HDIM / BN, BDIM / 128), NT, SMEM_M4>>>(
        (const __nv_bfloat16*)a0h, (const __nv_bfloat16*)a0l,
        (const __nv_bfloat16*)wh0, (const __nv_bfloat16*)wl0,
        (const float*)b0, DIN, HDIM, 1,
        (__nv_bfloat16*)a1h, (__nv_bfloat16*)a1l, nullptr);

    // layer 1: 128x128 tile, grid (16, 64)
    gemm_split_bf16<4><<<dim3(HDIM / BN, BDIM / 128), NT, SMEM_M4>>>(
        (const __nv_bfloat16*)a1h, (const __nv_bfloat16*)a1l,
        (const __nv_bfloat16*)wh1, (const __nv_bfloat16*)wl1,
        (const float*)b1, HDIM, HDIM, 1,
        (__nv_bfloat16*)a2h, (__nv_bfloat16*)a2l, nullptr);

    // layer 2 -> fp32 logits: 64x128 tile, grid (8, 128) = 1024 CTAs
    gemm_split_bf16<2><<<dim3(DOUT / BN, BDIM / 64), NT, SMEM_M2>>>(
        (const __nv_bfloat16*)a2h, (const __nv_bfloat16*)a2l,
        (const __nv_bfloat16*)wh2, (const __nv_bfloat16*)wl2,
        (const float*)b2, HDIM, DOUT, 0,
        nullptr, nullptr, (float*)d_out);

    // softmax in place
    softmax_kernel<<<BDIM, 256>>>((float*)d_out);
}

// round 15
// speedup vs baseline: 3.1647x; 1.0554x over previous
#include <cuda_runtime.h>
#include <cuda_bf16.h>
#include <cstdint>
#include <cstddef>

// ---------------------------------------------------------------------------
// Problem dims
// ---------------------------------------------------------------------------
#define BDIM   8192
#define DIN    2048
#define HDIM   2048
#define DOUT   1024
#define NCOMP  4

// ---------------------------------------------------------------------------
// Helpers (sm_103-safe)
// ---------------------------------------------------------------------------
__device__ __forceinline__ uint32_t smem_u32(const void* p) {
    uint32_t a;
    asm("{ .reg .u64 t; cvta.to.shared.u64 t, %1; cvt.u32.u64 %0, t; }"
        : "=r"(a) : "l"(p));
    return a;
}

#define SMEM_SWIZZLE_128B(o) ((o) ^ (((o) >> 3) & 0x70))

__device__ __forceinline__ void cp_async16(uint32_t dst, const void* src) {
    asm volatile("cp.async.cg.shared.global [%0], [%1], 16;"
                 :: "r"(dst), "l"(__cvta_generic_to_global(src)));
}
#define CP_COMMIT() asm volatile("cp.async.commit_group;" ::: "memory")
#define CP_WAIT(n)  asm volatile("cp.async.wait_group %0;" :: "n"(n) : "memory")

__device__ __forceinline__ void ldsm4(uint32_t* r, uint32_t addr) {
    asm volatile("ldmatrix.sync.aligned.m8n8.x4.shared.b16 {%0,%1,%2,%3}, [%4];"
                 : "=r"(r[0]), "=r"(r[1]), "=r"(r[2]), "=r"(r[3]) : "r"(addr));
}

__device__ __forceinline__ void mma16816(float* d, const uint32_t* a,
                                         uint32_t b0, uint32_t b1) {
    asm volatile(
        "mma.sync.aligned.m16n8k16.row.col.f32.bf16.bf16.f32 "
        "{%0,%1,%2,%3}, {%4,%5,%6,%7}, {%8,%9}, {%0,%1,%2,%3};"
        : "+f"(d[0]), "+f"(d[1]), "+f"(d[2]), "+f"(d[3])
        : "r"(a[0]), "r"(a[1]), "r"(a[2]), "r"(a[3]), "r"(b0), "r"(b1));
}

// ---------------------------------------------------------------------------
// Scratch buffers (__device__ globals; no cudaMalloc allowed)
// ---------------------------------------------------------------------------
__device__ __align__(16) __nv_bfloat16 g_wh0[HDIM * DIN];
__device__ __align__(16) __nv_bfloat16 g_wl0[HDIM * DIN];
__device__ __align__(16) __nv_bfloat16 g_wh1[HDIM * HDIM];
__device__ __align__(16) __nv_bfloat16 g_wl1[HDIM * HDIM];
__device__ __align__(16) __nv_bfloat16 g_wh2[DOUT * HDIM];
__device__ __align__(16) __nv_bfloat16 g_wl2[DOUT * HDIM];
__device__ __align__(16) float g_b0[HDIM];
__device__ __align__(16) float g_b1[HDIM];
__device__ __align__(16) float g_b2[DOUT];
__device__ __align__(16) __nv_bfloat16 g_a0h[BDIM * DIN];
__device__ __align__(16) __nv_bfloat16 g_a0l[BDIM * DIN];
__device__ __align__(16) __nv_bfloat16 g_a1h[BDIM * HDIM];
__device__ __align__(16) __nv_bfloat16 g_a1l[BDIM * HDIM];
__device__ __align__(16) __nv_bfloat16 g_a2h[BDIM * HDIM];
__device__ __align__(16) __nv_bfloat16 g_a2l[BDIM * HDIM];

// ---------------------------------------------------------------------------
// Prep: fold mixture into effective bf16 hi/lo weights + fp32 bias
// ---------------------------------------------------------------------------
__device__ __forceinline__ void mix_coefs(const float* ml, const float* lv,
                                          float* cmu, float* cn) {
    float m[NCOMP], mx = -1e30f, s = 0.f, e[NCOMP];
    #pragma unroll
    for (int k = 0; k < NCOMP; k++) { m[k] = ml[k]; mx = fmaxf(mx, m[k]); }
    #pragma unroll
    for (int k = 0; k < NCOMP; k++) { e[k] = expf(m[k] - mx); s += e[k]; }
    #pragma unroll
    for (int k = 0; k < NCOMP; k++) {
        float w = e[k] / s;
        cmu[k] = w;
        cn[k]  = w * expf(0.5f * lv[k]);
    }
}

__device__ __forceinline__ void split_store(const float4 acc,
                                            __nv_bfloat16* whi,
                                            __nv_bfloat16* wlo, size_t i) {
    __nv_bfloat16 h0 = __float2bfloat16(acc.x);
    __nv_bfloat16 h1 = __float2bfloat16(acc.y);
    __nv_bfloat16 h2 = __float2bfloat16(acc.z);
    __nv_bfloat16 h3 = __float2bfloat16(acc.w);
    __nv_bfloat16 l0 = __float2bfloat16(acc.x - __bfloat162float(h0));
    __nv_bfloat16 l1 = __float2bfloat16(acc.y - __bfloat162float(h1));
    __nv_bfloat16 l2 = __float2bfloat16(acc.z - __bfloat162float(h2));
    __nv_bfloat16 l3 = __float2bfloat16(acc.w - __bfloat162float(h3));
    ((__nv_bfloat162*)whi)[2 * i]     = __halves2bfloat162(h0, h1);
    ((__nv_bfloat162*)whi)[2 * i + 1] = __halves2bfloat162(h2, h3);
    ((__nv_bfloat162*)wlo)[2 * i]     = __halves2bfloat162(l0, l1);
    ((__nv_bfloat162*)wlo)[2 * i + 1] = __halves2bfloat162(l2, l3);
}

__device__ __forceinline__ float4 mix4(const float4* wmu, const float4* wn,
                                       size_t n4, size_t i,
                                       const float* cmu, const float* cn) {
    float4 acc = make_float4(0.f, 0.f, 0.f, 0.f);
    #pragma unroll
    for (int k = 0; k < NCOMP; k++) {
        float4 a = wmu[(size_t)k * n4 + i];
        float4 b = wn[(size_t)k * n4 + i];
        acc.x += cmu[k] * a.x + cn[k] * b.x;
        acc.y += cmu[k] * a.y + cn[k] * b.y;
        acc.z += cmu[k] * a.z + cn[k] * b.z;
        acc.w += cmu[k] * a.w + cn[k] * b.w;
    }
    return acc;
}

#define L0_F4 ((size_t)(HDIM) * DIN / 4)
#define L1_F4 ((size_t)(HDIM) * HDIM / 4)
#define L2_F4 ((size_t)(DOUT) * HDIM / 4)
#define PREP_BLOCKS ((int)((L0_F4 + L1_F4 + L2_F4) / 256))

__global__ void prep_weights_all_kernel(
    const float* __restrict__ wmu0, const float* __restrict__ wn0,
    const float* __restrict__ wlv0, const float* __restrict__ ml0,
    const float* __restrict__ wmu1, const float* __restrict__ wn1,
    const float* __restrict__ wlv1, const float* __restrict__ ml1,
    const float* __restrict__ wmu2, const float* __restrict__ wn2,
    const float* __restrict__ wlv2, const float* __restrict__ ml2,
    __nv_bfloat16* __restrict__ wh0, __nv_bfloat16* __restrict__ wl0,
    __nv_bfloat16* __restrict__ wh1, __nv_bfloat16* __restrict__ wl1,
    __nv_bfloat16* __restrict__ wh2, __nv_bfloat16* __restrict__ wl2) {
    __shared__ float cmu[NCOMP], cn[NCOMP];
    size_t g = (size_t)blockIdx.x * blockDim.x;
    const float4* wmu; const float4* wn; const float* wlv; const float* ml;
    __nv_bfloat16* wh; __nv_bfloat16* wl; size_t n4; size_t base;
    if (g < L0_F4) {
        wmu = (const float4*)wmu0; wn = (const float4*)wn0;
        wlv = wlv0; ml = ml0; wh = wh0; wl = wl0; n4 = L0_F4; base = g;
    } else if (g < L0_F4 + L1_F4) {
        wmu = (const float4*)wmu1; wn = (const float4*)wn1;
        wlv = wlv1; ml = ml1; wh = wh1; wl = wl1; n4 = L1_F4; base = g - L0_F4;
    } else {
        wmu = (const float4*)wmu2; wn = (const float4*)wn2;
        wlv = wlv2; ml = ml2; wh = wh2; wl = wl2; n4 = L2_F4;
        base = g - L0_F4 - L1_F4;
    }
    if (threadIdx.x == 0) mix_coefs(ml, wlv, cmu, cn);
    __syncthreads();
    size_t i = base + threadIdx.x;
    float4 acc = mix4(wmu, wn, n4, i, cmu, cn);
    split_store(acc, wh, wl, i);
}

__global__ void prep_bias_all_kernel(
    const float* __restrict__ bmu0, const float* __restrict__ bn0,
    const float* __restrict__ blv0, const float* __restrict__ ml0,
    const float* __restrict__ bmu1, const float* __restrict__ bn1,
    const float* __restrict__ blv1, const float* __restrict__ ml1,
    const float* __restrict__ bmu2, const float* __restrict__ bn2,
    const float* __restrict__ blv2, const float* __restrict__ ml2,
    float* __restrict__ b0, float* __restrict__ b1, float* __restrict__ b2) {
    __shared__ float cmu[NCOMP], cn[NCOMP];
    int g = blockIdx.x * blockDim.x + threadIdx.x;
    const float* bmu; const float* bn; const float* blv; const float* ml;
    float* out; int o; int O;
    if (g < HDIM)          { bmu = bmu0; bn = bn0; blv = blv0; ml = ml0; out = b0; o = g;            O = HDIM; }
    else if (g < 2 * HDIM) { bmu = bmu1; bn = bn1; blv = blv1; ml = ml1; out = b1; o = g - HDIM;     O = HDIM; }
    else                   { bmu = bmu2; bn = bn2; blv = blv2; ml = ml2; out = b2; o = g - 2 * HDIM; O = DOUT; }
    if (threadIdx.x == 0) mix_coefs(ml, blv, cmu, cn);
    __syncthreads();
    float e = 0.f;
    #pragma unroll
    for (int k = 0; k < NCOMP; k++)
        e += cmu[k] * bmu[k * O + o] + cn[k] * bn[k * O + o];
    out[o] = e;
}

__global__ void split_x_kernel(const float* __restrict__ x,
                               __nv_bfloat16* __restrict__ xh,
                               __nv_bfloat16* __restrict__ xl, int n) {
    size_t n4 = (size_t)(n >> 2);
    size_t stride = (size_t)gridDim.x * blockDim.x;
    for (size_t i = (size_t)blockIdx.x * blockDim.x + threadIdx.x; i < n4;
         i += 2 * stride) {
        size_t j = i + stride;
        float4 v0 = ((const float4*)x)[i];
        if (j < n4) {
            float4 v1 = ((const float4*)x)[j];
            split_store(v0, xh, xl, i);
            split_store(v1, xh, xl, j);
        } else {
            split_store(v0, xh, xl, i);
        }
    }
}

// ---------------------------------------------------------------------------
// mma.sync GEMM:  C[B,O] = A[B,I] @ W[O,I]^T + bias   (split bf16 hi/lo)
// PROVEN 2-stage / one-barrier pipeline; MFRAG=2 (64x128 tile, 48 KB stage)
// with __launch_bounds__(256, 2) -> 2 CTAs/SM so one CTA's MMAs cover the
// other CTA's barrier/wait window (tensor pipe was 74.8% at 1 CTA/SM).
// ---------------------------------------------------------------------------
#define BN 128
#define BK 64
#define NT 256

template <int MFRAG>
__global__ void __launch_bounds__(NT, (MFRAG == 2 ? 2 : 1))
gemm_split_bf16(const __nv_bfloat16* __restrict__ Ah,
                const __nv_bfloat16* __restrict__ Al,
                const __nv_bfloat16* __restrict__ Wh,
                const __nv_bfloat16* __restrict__ Wl,
                const float* __restrict__ bias,
                int Idim, int Odim, int relu_split,
                __nv_bfloat16* __restrict__ Oh,
                __nv_bfloat16* __restrict__ Ol,
                float* __restrict__ Of) {
    constexpr int BM = MFRAG * 32;
    constexpr int OFF_AL = BM * 128;
    constexpr int OFF_WH = 2 * BM * 128;
    constexpr int OFF_WL = 2 * BM * 128 + 16384;
    constexpr int STAGE  = 2 * BM * 128 + 32768;

    extern __shared__ char smem[];
    const uint32_t sb = smem_u32(smem);
    const int tid = threadIdx.x;
    const int wid = tid >> 5, l = tid & 31;
    const int n0 = blockIdx.x * BN, m0 = blockIdx.y * BM;
    const int wm = (wid >> 2) * (MFRAG * 16);
    const int wn = (wid & 3) * 32;
    const int lm = l >> 3, lr = l & 7;

    float acc[MFRAG][4][4];
    #pragma unroll
    for (int i = 0; i < MFRAG; i++)
        #pragma unroll
        for (int j = 0; j < 4; j++)
            #pragma unroll
            for (int q = 0; q < 4; q++) acc[i][j][q] = 0.f;

    const int nk = Idim / BK;

    auto issue = [&](int s, int k0) {
        uint32_t base = sb + s * STAGE;
        #pragma unroll
        for (int j = 0; j < MFRAG; j++) {
            int c = tid + j * NT;
            int row = c >> 3, col = c & 7;
            uint32_t so = SMEM_SWIZZLE_128B((uint32_t)(row * 128 + col * 16));
            size_t g = (size_t)(m0 + row) * Idim + k0 + col * 8;
            cp_async16(base + so, Ah + g);
            cp_async16(base + OFF_AL + so, Al + g);
        }
        #pragma unroll
        for (int j = 0; j < 4; j++) {
            int c = tid + j * NT;
            int row = c >> 3, col = c & 7;
            uint32_t so = SMEM_SWIZZLE_128B((uint32_t)(row * 128 + col * 16));
            size_t g = (size_t)(n0 + row) * Idim + k0 + col * 8;
            cp_async16(base + OFF_WH + so, Wh + g);
            cp_async16(base + OFF_WL + so, Wl + g);
        }
    };

    issue(0, 0);
    CP_COMMIT();

    for (int it = 0; it < nk; ++it) {
        CP_WAIT(0);
        __syncthreads();
        if (it + 1 < nk) {
            issue((it + 1) & 1, (it + 1) * BK);
            CP_COMMIT();
        }

        uint32_t bA = sb + (it & 1) * STAGE;
        #pragma unroll
        for (int kk = 0; kk < 4; kk++) {
            uint32_t ah[MFRAG][4], al[MFRAG][4];
            #pragma unroll
            for (int mf = 0; mf < MFRAG; mf++) {
                uint32_t off = SMEM_SWIZZLE_128B(
                    (uint32_t)((wm + mf * 16 + (lm & 1) * 8 + lr) * 128 +
                               (kk * 2 + (lm >> 1)) * 16));
                ldsm4(ah[mf], bA + off);
                ldsm4(al[mf], bA + OFF_AL + off);
            }
            #pragma unroll
            for (int nf2 = 0; nf2 < 2; nf2++) {
                uint32_t off = SMEM_SWIZZLE_128B(
                    (uint32_t)((wn + nf2 * 16 + (lm >> 1) * 8 + lr) * 128 +
                               (kk * 2 + (lm & 1)) * 16));
                uint32_t bh[4], bl[4];
                ldsm4(bh, bA + OFF_WH + off);
                ldsm4(bl, bA + OFF_WL + off);
                #pragma unroll
                for (int mf = 0; mf < MFRAG; mf++) {
                    mma16816(acc[mf][2 * nf2],     ah[mf], bh[0], bh[1]);
                    mma16816(acc[mf][2 * nf2 + 1], ah[mf], bh[2], bh[3]);
                }
                #pragma unroll
                for (int mf = 0; mf < MFRAG; mf++) {
                    mma16816(acc[mf][2 * nf2],     ah[mf], bl[0], bl[1]);
                    mma16816(acc[mf][2 * nf2 + 1], ah[mf], bl[2], bl[3]);
                }
                #pragma unroll
                for (int mf = 0; mf < MFRAG; mf++) {
                    mma16816(acc[mf][2 * nf2],     al[mf], bh[0], bh[1]);
                    mma16816(acc[mf][2 * nf2 + 1], al[mf], bh[2], bh[3]);
                }
            }
        }
    }

    // Epilogue
    const int cb = n0 + wn;
    if (relu_split) {
        #pragma unroll
        for (int mf = 0; mf < MFRAG; mf++) {
            int r0 = m0 + wm + mf * 16 + (l >> 2);
            #pragma unroll
            for (int nf = 0; nf < 4; nf++) {
                int col = cb + nf * 8 + 2 * (l & 3);
                float2 bv = *(const float2*)(bias + col);
                float v0 = fmaxf(acc[mf][nf][0] + bv.x, 0.f);
                float v1 = fmaxf(acc[mf][nf][1] + bv.y, 0.f);
                float v2 = fmaxf(acc[mf][nf][2] + bv.x, 0.f);
                float v3 = fmaxf(acc[mf][nf][3] + bv.y, 0.f);
                __nv_bfloat16 h0 = __float2bfloat16(v0);
                __nv_bfloat16 h1 = __float2bfloat16(v1);
                __nv_bfloat16 h2 = __float2bfloat16(v2);
                __nv_bfloat16 h3 = __float2bfloat16(v3);
                __nv_bfloat16 q0 = __float2bfloat16(v0 - __bfloat162float(h0));
                __nv_bfloat16 q1 = __float2bfloat16(v1 - __bfloat162float(h1));
                __nv_bfloat16 q2 = __float2bfloat16(v2 - __bfloat162float(h2));
                __nv_bfloat16 q3 = __float2bfloat16(v3 - __bfloat162float(h3));
                *(__nv_bfloat162*)(Oh + (size_t)r0 * Odim + col) = __halves2bfloat162(h0, h1);
                *(__nv_bfloat162*)(Oh + (size_t)(r0 + 8) * Odim + col) = __halves2bfloat162(h2, h3);
                *(__nv_bfloat162*)(Ol + (size_t)r0 * Odim + col) = __halves2bfloat162(q0, q1);
                *(__nv_bfloat162*)(Ol + (size_t)(r0 + 8) * Odim + col) = __halves2bfloat162(q2, q3);
            }
        }
    } else {
        #pragma unroll
        for (int mf = 0; mf < MFRAG; mf++) {
            int r0 = m0 + wm + mf * 16 + (l >> 2);
            #pragma unroll
            for (int nf = 0; nf < 4; nf++) {
                int col = cb + nf * 8 + 2 * (l & 3);
                float2 bv = *(const float2*)(bias + col);
                float2 o0 = make_float2(acc[mf][nf][0] + bv.x, acc[mf][nf][1] + bv.y);
                float2 o1 = make_float2(acc[mf][nf][2] + bv.x, acc[mf][nf][3] + bv.y);
                *(float2*)(Of + (size_t)r0 * Odim + col) = o0;
                *(float2*)(Of + (size_t)(r0 + 8) * Odim + col) = o1;
            }
        }
    }
}

#define SMEM_M2 (2 * (2 * 64 * 128 + 32768))    // 96 KB -> 2 CTAs/SM

// ---------------------------------------------------------------------------
// Row softmax (in-place), 1024 cols, 256 threads/row, float4 I/O
// ---------------------------------------------------------------------------
__global__ void softmax_kernel(float* __restrict__ io) {
    __shared__ float red[8];
    int b = blockIdx.x;
    float* row = io + (size_t)b * DOUT;
    int t = threadIdx.x;
    float4 v = ((const float4*)row)[t];
    float m = fmaxf(fmaxf(v.x, v.y), fmaxf(v.z, v.w));
    #pragma unroll
    for (int o = 16; o; o >>= 1) m = fmaxf(m, __shfl_xor_sync(0xffffffffu, m, o));
    if ((t & 31) == 0) red[t >> 5] = m;
    __syncthreads();
    m = red[0];
    #pragma unroll
    for (int w = 1; w < 8; w++) m = fmaxf(m, red[w]);
    v.x = expf(v.x - m); v.y = expf(v.y - m);
    v.z = expf(v.z - m); v.w = expf(v.w - m);
    float s = v.x + v.y + v.z + v.w;
    #pragma unroll
    for (int o = 16; o; o >>= 1) s += __shfl_xor_sync(0xffffffffu, s, o);
    __syncthreads();
    if ((t & 31) == 0) red[t >> 5] = s;
    __syncthreads();
    s = red[0];
    #pragma unroll
    for (int w = 1; w < 8; w++) s += red[w];
    float inv = 1.0f / s;
    v.x *= inv; v.y *= inv; v.z *= inv; v.w *= inv;
    ((float4*)row)[t] = v;
}

// ---------------------------------------------------------------------------
// Launcher
// ---------------------------------------------------------------------------
extern "C" void kernel_launch(void* const* d_in, const int* in_sizes, int n_in,
                              void* d_out, int out_size) {
    (void)in_sizes; (void)n_in; (void)out_size;
    const float* x   = (const float*)d_in[0];
    const float* wmu[3] = {(const float*)d_in[1],  (const float*)d_in[8],  (const float*)d_in[15]};
    const float* bmu[3] = {(const float*)d_in[2],  (const float*)d_in[9],  (const float*)d_in[16]};
    const float* wlv[3] = {(const float*)d_in[3],  (const float*)d_in[10], (const float*)d_in[17]};
    const float* blv[3] = {(const float*)d_in[4],  (const float*)d_in[11], (const float*)d_in[18]};
    const float* ml[3]  = {(const float*)d_in[5],  (const float*)d_in[12], (const float*)d_in[19]};
    const float* wn[3]  = {(const float*)d_in[6],  (const float*)d_in[13], (const float*)d_in[20]};
    const float* bn[3]  = {(const float*)d_in[7],  (const float*)d_in[14], (const float*)d_in[21]};

    void *wh0, *wl0, *wh1, *wl1, *wh2, *wl2, *b0, *b1, *b2;
    void *a0h, *a0l, *a1h, *a1l, *a2h, *a2l;
    cudaGetSymbolAddress(&wh0, g_wh0); cudaGetSymbolAddress(&wl0, g_wl0);
    cudaGetSymbolAddress(&wh1, g_wh1); cudaGetSymbolAddress(&wl1, g_wl1);
    cudaGetSymbolAddress(&wh2, g_wh2); cudaGetSymbolAddress(&wl2, g_wl2);
    cudaGetSymbolAddress(&b0, g_b0);   cudaGetSymbolAddress(&b1, g_b1);
    cudaGetSymbolAddress(&b2, g_b2);
    cudaGetSymbolAddress(&a0h, g_a0h); cudaGetSymbolAddress(&a0l, g_a0l);
    cudaGetSymbolAddress(&a1h, g_a1h); cudaGetSymbolAddress(&a1l, g_a1l);
    cudaGetSymbolAddress(&a2h, g_a2h); cudaGetSymbolAddress(&a2l, g_a2l);

    cudaFuncSetAttribute(gemm_split_bf16<2>,
                         cudaFuncAttributeMaxDynamicSharedMemorySize, SMEM_M2);

    // prep: input split, all weights (one launch), all biases (one launch)
    split_x_kernel<<<1024, 256>>>(x, (__nv_bfloat16*)a0h, (__nv_bfloat16*)a0l, BDIM * DIN);
    prep_weights_all_kernel<<<PREP_BLOCKS, 256>>>(
        wmu[0], wn[0], wlv[0], ml[0],
        wmu[1], wn[1], wlv[1], ml[1],
        wmu[2], wn[2], wlv[2], ml[2],
        (__nv_bfloat16*)wh0, (__nv_bfloat16*)wl0,
        (__nv_bfloat16*)wh1, (__nv_bfloat16*)wl1,
        (__nv_bfloat16*)wh2, (__nv_bfloat16*)wl2);
    prep_bias_all_kernel<<<(2 * HDIM + DOUT) / 256, 256>>>(
        bmu[0], bn[0], blv[0], ml[0],
        bmu[1], bn[1], blv[1], ml[1],
        bmu[2], bn[2], blv[2], ml[2],
        (float*)b0, (float*)b1, (float*)b2);

    // layer 0: 64x128 tile, grid (16, 128) = 2048 CTAs, 2 CTAs/SM
    gemm_split_bf16<2><<<dim3(HDIM / BN, BDIM / 64), NT, SMEM_M2>>>(
        (const __nv_bfloat16*)a0h, (const __nv_bfloat16*)a0l,
        (const __nv_bfloat16*)wh0, (const __nv_bfloat16*)wl0,
        (const float*)b0, DIN, HDIM, 1,
        (__nv_bfloat16*)a1h, (__nv_bfloat16*)a1l, nullptr);

    // layer 1: grid (16, 128)
    gemm_split_bf16<2><<<dim3(HDIM / BN, BDIM / 64), NT, SMEM_M2>>>(
        (const __nv_bfloat16*)a1h, (const __nv_bfloat16*)a1l,
        (const __nv_bfloat16*)wh1, (const __nv_bfloat16*)wl1,
        (const float*)b1, HDIM, HDIM, 1,
        (__nv_bfloat16*)a2h, (__nv_bfloat16*)a2l, nullptr);

    // layer 2 -> fp32 logits: grid (8, 128)
    gemm_split_bf16<2><<<dim3(DOUT / BN, BDIM / 64), NT, SMEM_M2>>>(
        (const __nv_bfloat16*)a2h, (const __nv_bfloat16*)a2l,
        (const __nv_bfloat16*)wh2, (const __nv_bfloat16*)wl2,
        (const float*)b2, HDIM, DOUT, 0,
        nullptr, nullptr, (float*)d_out);

    // softmax in place
    softmax_kernel<<<BDIM, 256>>>((float*)d_out);
}

// round 16
// speedup vs baseline: 3.1667x; 1.0006x over previous
#include <cuda_runtime.h>
#include <cuda_bf16.h>
#include <cstdint>
#include <cstddef>

// ---------------------------------------------------------------------------
// Problem dims
// ---------------------------------------------------------------------------
#define BDIM   8192
#define DIN    2048
#define HDIM   2048
#define DOUT   1024
#define NCOMP  4

// ---------------------------------------------------------------------------
// Helpers (sm_103-safe)
// ---------------------------------------------------------------------------
__device__ __forceinline__ uint32_t smem_u32(const void* p) {
    uint32_t a;
    asm("{ .reg .u64 t; cvta.to.shared.u64 t, %1; cvt.u32.u64 %0, t; }"
        : "=r"(a) : "l"(p));
    return a;
}

#define SMEM_SWIZZLE_128B(o) ((o) ^ (((o) >> 3) & 0x70))

__device__ __forceinline__ void cp_async16(uint32_t dst, const void* src) {
    asm volatile("cp.async.cg.shared.global [%0], [%1], 16;"
                 :: "r"(dst), "l"(__cvta_generic_to_global(src)));
}
#define CP_COMMIT() asm volatile("cp.async.commit_group;" ::: "memory")
#define CP_WAIT(n)  asm volatile("cp.async.wait_group %0;" :: "n"(n) : "memory")

__device__ __forceinline__ void ldsm4(uint32_t* r, uint32_t addr) {
    asm volatile("ldmatrix.sync.aligned.m8n8.x4.shared.b16 {%0,%1,%2,%3}, [%4];"
                 : "=r"(r[0]), "=r"(r[1]), "=r"(r[2]), "=r"(r[3]) : "r"(addr));
}

__device__ __forceinline__ void mma16816(float* d, const uint32_t* a,
                                         uint32_t b0, uint32_t b1) {
    asm volatile(
        "mma.sync.aligned.m16n8k16.row.col.f32.bf16.bf16.f32 "
        "{%0,%1,%2,%3}, {%4,%5,%6,%7}, {%8,%9}, {%0,%1,%2,%3};"
        : "+f"(d[0]), "+f"(d[1]), "+f"(d[2]), "+f"(d[3])
        : "r"(a[0]), "r"(a[1]), "r"(a[2]), "r"(a[3]), "r"(b0), "r"(b1));
}

// ---------------------------------------------------------------------------
// Scratch buffers (__device__ globals; no cudaMalloc allowed)
// ---------------------------------------------------------------------------
__device__ __align__(16) __nv_bfloat16 g_wh0[HDIM * DIN];
__device__ __align__(16) __nv_bfloat16 g_wl0[HDIM * DIN];
__device__ __align__(16) __nv_bfloat16 g_wh1[HDIM * HDIM];
__device__ __align__(16) __nv_bfloat16 g_wl1[HDIM * HDIM];
__device__ __align__(16) __nv_bfloat16 g_wh2[DOUT * HDIM];
__device__ __align__(16) __nv_bfloat16 g_wl2[DOUT * HDIM];
__device__ __align__(16) float g_b0[HDIM];
__device__ __align__(16) float g_b1[HDIM];
__device__ __align__(16) float g_b2[DOUT];
__device__ __align__(16) __nv_bfloat16 g_a0h[BDIM * DIN];
__device__ __align__(16) __nv_bfloat16 g_a0l[BDIM * DIN];
__device__ __align__(16) __nv_bfloat16 g_a1h[BDIM * HDIM];
__device__ __align__(16) __nv_bfloat16 g_a1l[BDIM * HDIM];
__device__ __align__(16) __nv_bfloat16 g_a2h[BDIM * HDIM];
__device__ __align__(16) __nv_bfloat16 g_a2l[BDIM * HDIM];

// ---------------------------------------------------------------------------
// Prep: fold mixture into effective bf16 hi/lo weights + fp32 bias
// ---------------------------------------------------------------------------
__device__ __forceinline__ void mix_coefs(const float* ml, const float* lv,
                                          float* cmu, float* cn) {
    float m[NCOMP], mx = -1e30f, s = 0.f, e[NCOMP];
    #pragma unroll
    for (int k = 0; k < NCOMP; k++) { m[k] = ml[k]; mx = fmaxf(mx, m[k]); }
    #pragma unroll
    for (int k = 0; k < NCOMP; k++) { e[k] = expf(m[k] - mx); s += e[k]; }
    #pragma unroll
    for (int k = 0; k < NCOMP; k++) {
        float w = e[k] / s;
        cmu[k] = w;
        cn[k]  = w * expf(0.5f * lv[k]);
    }
}

__device__ __forceinline__ void split_store(const float4 acc,
                                            __nv_bfloat16* whi,
                                            __nv_bfloat16* wlo, size_t i) {
    __nv_bfloat16 h0 = __float2bfloat16(acc.x);
    __nv_bfloat16 h1 = __float2bfloat16(acc.y);
    __nv_bfloat16 h2 = __float2bfloat16(acc.z);
    __nv_bfloat16 h3 = __float2bfloat16(acc.w);
    __nv_bfloat16 l0 = __float2bfloat16(acc.x - __bfloat162float(h0));
    __nv_bfloat16 l1 = __float2bfloat16(acc.y - __bfloat162float(h1));
    __nv_bfloat16 l2 = __float2bfloat16(acc.z - __bfloat162float(h2));
    __nv_bfloat16 l3 = __float2bfloat16(acc.w - __bfloat162float(h3));
    ((__nv_bfloat162*)whi)[2 * i]     = __halves2bfloat162(h0, h1);
    ((__nv_bfloat162*)whi)[2 * i + 1] = __halves2bfloat162(h2, h3);
    ((__nv_bfloat162*)wlo)[2 * i]     = __halves2bfloat162(l0, l1);
    ((__nv_bfloat162*)wlo)[2 * i + 1] = __halves2bfloat162(l2, l3);
}

__device__ __forceinline__ float4 mix4(const float4* wmu, const float4* wn,
                                       size_t n4, size_t i,
                                       const float* cmu, const float* cn) {
    float4 acc = make_float4(0.f, 0.f, 0.f, 0.f);
    #pragma unroll
    for (int k = 0; k < NCOMP; k++) {
        float4 a = wmu[(size_t)k * n4 + i];
        float4 b = wn[(size_t)k * n4 + i];
        acc.x += cmu[k] * a.x + cn[k] * b.x;
        acc.y += cmu[k] * a.y + cn[k] * b.y;
        acc.z += cmu[k] * a.z + cn[k] * b.z;
        acc.w += cmu[k] * a.w + cn[k] * b.w;
    }
    return acc;
}

// Per-layer weight fold (2 float4/thread ILP)
__global__ void prep_weights_kernel(const float* __restrict__ wmu,
                                    const float* __restrict__ wn,
                                    const float* __restrict__ wlv,
                                    const float* __restrict__ ml,
                                    __nv_bfloat16* __restrict__ whi,
                                    __nv_bfloat16* __restrict__ wlo,
                                    int n) {
    __shared__ float cmu[NCOMP], cn[NCOMP];
    if (threadIdx.x == 0) mix_coefs(ml, wlv, cmu, cn);
    __syncthreads();
    size_t n4 = (size_t)(n >> 2);
    size_t stride = (size_t)gridDim.x * blockDim.x;
    for (size_t i = (size_t)blockIdx.x * blockDim.x + threadIdx.x; i < n4;
         i += 2 * stride) {
        size_t j = i + stride;
        float4 a0 = mix4((const float4*)wmu, (const float4*)wn, n4, i, cmu, cn);
        if (j < n4) {
            float4 a1 = mix4((const float4*)wmu, (const float4*)wn, n4, j, cmu, cn);
            split_store(a0, whi, wlo, i);
            split_store(a1, whi, wlo, j);
        } else {
            split_store(a0, whi, wlo, i);
        }
    }
}

__global__ void prep_bias_all_kernel(
    const float* __restrict__ bmu0, const float* __restrict__ bn0,
    const float* __restrict__ blv0, const float* __restrict__ ml0,
    const float* __restrict__ bmu1, const float* __restrict__ bn1,
    const float* __restrict__ blv1, const float* __restrict__ ml1,
    const float* __restrict__ bmu2, const float* __restrict__ bn2,
    const float* __restrict__ blv2, const float* __restrict__ ml2,
    float* __restrict__ b0, float* __restrict__ b1, float* __restrict__ b2) {
    __shared__ float cmu[NCOMP], cn[NCOMP];
    int g = blockIdx.x * blockDim.x + threadIdx.x;
    const float* bmu; const float* bn; const float* blv; const float* ml;
    float* out; int o; int O;
    if (g < HDIM)          { bmu = bmu0; bn = bn0; blv = blv0; ml = ml0; out = b0; o = g;            O = HDIM; }
    else if (g < 2 * HDIM) { bmu = bmu1; bn = bn1; blv = blv1; ml = ml1; out = b1; o = g - HDIM;     O = HDIM; }
    else                   { bmu = bmu2; bn = bn2; blv = blv2; ml = ml2; out = b2; o = g - 2 * HDIM; O = DOUT; }
    if (threadIdx.x == 0) mix_coefs(ml, blv, cmu, cn);
    __syncthreads();
    float e = 0.f;
    #pragma unroll
    for (int k = 0; k < NCOMP; k++)
        e += cmu[k] * bmu[k * O + o] + cn[k] * bn[k * O + o];
    out[o] = e;
}

__global__ void split_x_kernel(const float* __restrict__ x,
                               __nv_bfloat16* __restrict__ xh,
                               __nv_bfloat16* __restrict__ xl, int n) {
    size_t n4 = (size_t)(n >> 2);
    size_t stride = (size_t)gridDim.x * blockDim.x;
    for (size_t i = (size_t)blockIdx.x * blockDim.x + threadIdx.x; i < n4;
         i += 2 * stride) {
        size_t j = i + stride;
        float4 v0 = ((const float4*)x)[i];
        if (j < n4) {
            float4 v1 = ((const float4*)x)[j];
            split_store(v0, xh, xl, i);
            split_store(v1, xh, xl, j);
        } else {
            split_store(v0, xh, xl, i);
        }
    }
}

// ---------------------------------------------------------------------------
// mma.sync GEMM — EXACT R15 winner: MFRAG=2, 64x128 tile, 2-stage pipeline,
// one barrier/iter, __launch_bounds__(256, 2) -> 2 CTAs/SM.
// ---------------------------------------------------------------------------
#define BN 128
#define BK 64
#define NT 256

template <int MFRAG>
__global__ void __launch_bounds__(NT, (MFRAG == 2 ? 2 : 1))
gemm_split_bf16(const __nv_bfloat16* __restrict__ Ah,
                const __nv_bfloat16* __restrict__ Al,
                const __nv_bfloat16* __restrict__ Wh,
                const __nv_bfloat16* __restrict__ Wl,
                const float* __restrict__ bias,
                int Idim, int Odim, int relu_split,
                __nv_bfloat16* __restrict__ Oh,
                __nv_bfloat16* __restrict__ Ol,
                float* __restrict__ Of) {
    constexpr int BM = MFRAG * 32;
    constexpr int OFF_AL = BM * 128;
    constexpr int OFF_WH = 2 * BM * 128;
    constexpr int OFF_WL = 2 * BM * 128 + 16384;
    constexpr int STAGE  = 2 * BM * 128 + 32768;

    extern __shared__ char smem[];
    const uint32_t sb = smem_u32(smem);
    const int tid = threadIdx.x;
    const int wid = tid >> 5, l = tid & 31;
    const int n0 = blockIdx.x * BN, m0 = blockIdx.y * BM;
    const int wm = (wid >> 2) * (MFRAG * 16);
    const int wn = (wid & 3) * 32;
    const int lm = l >> 3, lr = l & 7;

    float acc[MFRAG][4][4];
    #pragma unroll
    for (int i = 0; i < MFRAG; i++)
        #pragma unroll
        for (int j = 0; j < 4; j++)
            #pragma unroll
            for (int q = 0; q < 4; q++) acc[i][j][q] = 0.f;

    const int nk = Idim / BK;

    auto issue = [&](int s, int k0) {
        uint32_t base = sb + s * STAGE;
        #pragma unroll
        for (int j = 0; j < MFRAG; j++) {
            int c = tid + j * NT;
            int row = c >> 3, col = c & 7;
            uint32_t so = SMEM_SWIZZLE_128B((uint32_t)(row * 128 + col * 16));
            size_t g = (size_t)(m0 + row) * Idim + k0 + col * 8;
            cp_async16(base + so, Ah + g);
            cp_async16(base + OFF_AL + so, Al + g);
        }
        #pragma unroll
        for (int j = 0; j < 4; j++) {
            int c = tid + j * NT;
            int row = c >> 3, col = c & 7;
            uint32_t so = SMEM_SWIZZLE_128B((uint32_t)(row * 128 + col * 16));
            size_t g = (size_t)(n0 + row) * Idim + k0 + col * 8;
            cp_async16(base + OFF_WH + so, Wh + g);
            cp_async16(base + OFF_WL + so, Wl + g);
        }
    };

    issue(0, 0);
    CP_COMMIT();

    for (int it = 0; it < nk; ++it) {
        CP_WAIT(0);
        __syncthreads();
        if (it + 1 < nk) {
            issue((it + 1) & 1, (it + 1) * BK);
            CP_COMMIT();
        }

        uint32_t bA = sb + (it & 1) * STAGE;
        #pragma unroll
        for (int kk = 0; kk < 4; kk++) {
            uint32_t ah[MFRAG][4], al[MFRAG][4];
            #pragma unroll
            for (int mf = 0; mf < MFRAG; mf++) {
                uint32_t off = SMEM_SWIZZLE_128B(
                    (uint32_t)((wm + mf * 16 + (lm & 1) * 8 + lr) * 128 +
                               (kk * 2 + (lm >> 1)) * 16));
                ldsm4(ah[mf], bA + off);
                ldsm4(al[mf], bA + OFF_AL + off);
            }
            #pragma unroll
            for (int nf2 = 0; nf2 < 2; nf2++) {
                uint32_t off = SMEM_SWIZZLE_128B(
                    (uint32_t)((wn + nf2 * 16 + (lm >> 1) * 8 + lr) * 128 +
                               (kk * 2 + (lm & 1)) * 16));
                uint32_t bh[4], bl[4];
                ldsm4(bh, bA + OFF_WH + off);
                ldsm4(bl, bA + OFF_WL + off);
                #pragma unroll
                for (int mf = 0; mf < MFRAG; mf++) {
                    mma16816(acc[mf][2 * nf2],     ah[mf], bh[0], bh[1]);
                    mma16816(acc[mf][2 * nf2 + 1], ah[mf], bh[2], bh[3]);
                }
                #pragma unroll
                for (int mf = 0; mf < MFRAG; mf++) {
                    mma16816(acc[mf][2 * nf2],     ah[mf], bl[0], bl[1]);
                    mma16816(acc[mf][2 * nf2 + 1], ah[mf], bl[2], bl[3]);
                }
                #pragma unroll
                for (int mf = 0; mf < MFRAG; mf++) {
                    mma16816(acc[mf][2 * nf2],     al[mf], bh[0], bh[1]);
                    mma16816(acc[mf][2 * nf2 + 1], al[mf], bh[2], bh[3]);
                }
            }
        }
    }

    // Epilogue
    const int cb = n0 + wn;
    if (relu_split) {
        #pragma unroll
        for (int mf = 0; mf < MFRAG; mf++) {
            int r0 = m0 + wm + mf * 16 + (l >> 2);
            #pragma unroll
            for (int nf = 0; nf < 4; nf++) {
                int col = cb + nf * 8 + 2 * (l & 3);
                float2 bv = *(const float2*)(bias + col);
                float v0 = fmaxf(acc[mf][nf][0] + bv.x, 0.f);
                float v1 = fmaxf(acc[mf][nf][1] + bv.y, 0.f);
                float v2 = fmaxf(acc[mf][nf][2] + bv.x, 0.f);
                float v3 = fmaxf(acc[mf][nf][3] + bv.y, 0.f);
                __nv_bfloat16 h0 = __float2bfloat16(v0);
                __nv_bfloat16 h1 = __float2bfloat16(v1);
                __nv_bfloat16 h2 = __float2bfloat16(v2);
                __nv_bfloat16 h3 = __float2bfloat16(v3);
                __nv_bfloat16 q0 = __float2bfloat16(v0 - __bfloat162float(h0));
                __nv_bfloat16 q1 = __float2bfloat16(v1 - __bfloat162float(h1));
                __nv_bfloat16 q2 = __float2bfloat16(v2 - __bfloat162float(h2));
                __nv_bfloat16 q3 = __float2bfloat16(v3 - __bfloat162float(h3));
                *(__nv_bfloat162*)(Oh + (size_t)r0 * Odim + col) = __halves2bfloat162(h0, h1);
                *(__nv_bfloat162*)(Oh + (size_t)(r0 + 8) * Odim + col) = __halves2bfloat162(h2, h3);
                *(__nv_bfloat162*)(Ol + (size_t)r0 * Odim + col) = __halves2bfloat162(q0, q1);
                *(__nv_bfloat162*)(Ol + (size_t)(r0 + 8) * Odim + col) = __halves2bfloat162(q2, q3);
            }
        }
    } else {
        #pragma unroll
        for (int mf = 0; mf < MFRAG; mf++) {
            int r0 = m0 + wm + mf * 16 + (l >> 2);
            #pragma unroll
            for (int nf = 0; nf < 4; nf++) {
                int col = cb + nf * 8 + 2 * (l & 3);
                float2 bv = *(const float2*)(bias + col);
                float2 o0 = make_float2(acc[mf][nf][0] + bv.x, acc[mf][nf][1] + bv.y);
                float2 o1 = make_float2(acc[mf][nf][2] + bv.x, acc[mf][nf][3] + bv.y);
                *(float2*)(Of + (size_t)r0 * Odim + col) = o0;
                *(float2*)(Of + (size_t)(r0 + 8) * Odim + col) = o1;
            }
        }
    }
}

#define SMEM_M2 (2 * (2 * 64 * 128 + 32768))    // 96 KB -> 2 CTAs/SM

// ---------------------------------------------------------------------------
// Row softmax (in-place), 1024 cols, 256 threads/row, float4 I/O
// ---------------------------------------------------------------------------
__global__ void softmax_kernel(float* __restrict__ io) {
    __shared__ float red[8];
    int b = blockIdx.x;
    float* row = io + (size_t)b * DOUT;
    int t = threadIdx.x;
    float4 v = ((const float4*)row)[t];
    float m = fmaxf(fmaxf(v.x, v.y), fmaxf(v.z, v.w));
    #pragma unroll
    for (int o = 16; o; o >>= 1) m = fmaxf(m, __shfl_xor_sync(0xffffffffu, m, o));
    if ((t & 31) == 0) red[t >> 5] = m;
    __syncthreads();
    m = red[0];
    #pragma unroll
    for (int w = 1; w < 8; w++) m = fmaxf(m, red[w]);
    v.x = expf(v.x - m); v.y = expf(v.y - m);
    v.z = expf(v.z - m); v.w = expf(v.w - m);
    float s = v.x + v.y + v.z + v.w;
    #pragma unroll
    for (int o = 16; o; o >>= 1) s += __shfl_xor_sync(0xffffffffu, s, o);
    __syncthreads();
    if ((t & 31) == 0) red[t >> 5] = s;
    __syncthreads();
    s = red[0];
    #pragma unroll
    for (int w = 1; w < 8; w++) s += red[w];
    float inv = 1.0f / s;
    v.x *= inv; v.y *= inv; v.z *= inv; v.w *= inv;
    ((float4*)row)[t] = v;
}

// ---------------------------------------------------------------------------
// Launcher — fork/join: prep for layers 1/2 runs on a side stream overlapping
// gemm0; event joins gate gemm1/gemm2. GEMM kernels unchanged from R15.
// ---------------------------------------------------------------------------
extern "C" void kernel_launch(void* const* d_in, const int* in_sizes, int n_in,
                              void* d_out, int out_size) {
    (void)in_sizes; (void)n_in; (void)out_size;
    const float* x   = (const float*)d_in[0];
    const float* wmu[3] = {(const float*)d_in[1],  (const float*)d_in[8],  (const float*)d_in[15]};
    const float* bmu[3] = {(const float*)d_in[2],  (const float*)d_in[9],  (const float*)d_in[16]};
    const float* wlv[3] = {(const float*)d_in[3],  (const float*)d_in[10], (const float*)d_in[17]};
    const float* blv[3] = {(const float*)d_in[4],  (const float*)d_in[11], (const float*)d_in[18]};
    const float* ml[3]  = {(const float*)d_in[5],  (const float*)d_in[12], (const float*)d_in[19]};
    const float* wn[3]  = {(const float*)d_in[6],  (const float*)d_in[13], (const float*)d_in[20]};
    const float* bn[3]  = {(const float*)d_in[7],  (const float*)d_in[14], (const float*)d_in[21]};

    void *wh0, *wl0, *wh1, *wl1, *wh2, *wl2, *b0, *b1, *b2;
    void *a0h, *a0l, *a1h, *a1l, *a2h, *a2l;
    cudaGetSymbolAddress(&wh0, g_wh0); cudaGetSymbolAddress(&wl0, g_wl0);
    cudaGetSymbolAddress(&wh1, g_wh1); cudaGetSymbolAddress(&wl1, g_wl1);
    cudaGetSymbolAddress(&wh2, g_wh2); cudaGetSymbolAddress(&wl2, g_wl2);
    cudaGetSymbolAddress(&b0, g_b0);   cudaGetSymbolAddress(&b1, g_b1);
    cudaGetSymbolAddress(&b2, g_b2);
    cudaGetSymbolAddress(&a0h, g_a0h); cudaGetSymbolAddress(&a0l, g_a0l);
    cudaGetSymbolAddress(&a1h, g_a1h); cudaGetSymbolAddress(&a1l, g_a1l);
    cudaGetSymbolAddress(&a2h, g_a2h); cudaGetSymbolAddress(&a2l, g_a2l);

    cudaFuncSetAttribute(gemm_split_bf16<2>,
                         cudaFuncAttributeMaxDynamicSharedMemorySize, SMEM_M2);

    // One-time stream/event creation (host resources, no device memory)
    static cudaStream_t s_side = nullptr;
    static cudaEvent_t ev_fork = nullptr, ev_w1 = nullptr, ev_w2 = nullptr;
    if (s_side == nullptr) {
        cudaStreamCreateWithFlags(&s_side, cudaStreamNonBlocking);
        cudaEventCreateWithFlags(&ev_fork, cudaEventDisableTiming);
        cudaEventCreateWithFlags(&ev_w1,  cudaEventDisableTiming);
        cudaEventCreateWithFlags(&ev_w2,  cudaEventDisableTiming);
    }

    // Fork side stream into the capture
    cudaEventRecord(ev_fork, 0);
    cudaStreamWaitEvent(s_side, ev_fork, 0);

    // Side stream: weights for layers 1 and 2 (overlaps gemm0)
    prep_weights_kernel<<<1024, 256, 0, s_side>>>(
        wmu[1], wn[1], wlv[1], ml[1],
        (__nv_bfloat16*)wh1, (__nv_bfloat16*)wl1, HDIM * HDIM);
    cudaEventRecord(ev_w1, s_side);
    prep_weights_kernel<<<1024, 256, 0, s_side>>>(
        wmu[2], wn[2], wlv[2], ml[2],
        (__nv_bfloat16*)wh2, (__nv_bfloat16*)wl2, DOUT * HDIM);
    cudaEventRecord(ev_w2, s_side);

    // Main stream: only what gemm0 needs
    split_x_kernel<<<1024, 256>>>(x, (__nv_bfloat16*)a0h, (__nv_bfloat16*)a0l, BDIM * DIN);
    prep_weights_kernel<<<1024, 256>>>(
        wmu[0], wn[0], wlv[0], ml[0],
        (__nv_bfloat16*)wh0, (__nv_bfloat16*)wl0, HDIM * DIN);
    prep_bias_all_kernel<<<(2 * HDIM + DOUT) / 256, 256>>>(
        bmu[0], bn[0], blv[0], ml[0],
        bmu[1], bn[1], blv[1], ml[1],
        bmu[2], bn[2], blv[2], ml[2],
        (float*)b0, (float*)b1, (float*)b2);

    // layer 0: 64x128 tile, grid (16, 128) = 2048 CTAs, 2 CTAs/SM
    gemm_split_bf16<2><<<dim3(HDIM / BN, BDIM / 64), NT, SMEM_M2>>>(
        (const __nv_bfloat16*)a0h, (const __nv_bfloat16*)a0l,
        (const __nv_bfloat16*)wh0, (const __nv_bfloat16*)wl0,
        (const float*)b0, DIN, HDIM, 1,
        (__nv_bfloat16*)a1h, (__nv_bfloat16*)a1l, nullptr);

    // join: wh1/wl1 ready
    cudaStreamWaitEvent(0, ev_w1, 0);
    gemm_split_bf16<2><<<dim3(HDIM / BN, BDIM / 64), NT, SMEM_M2>>>(
        (const __nv_bfloat16*)a1h, (const __nv_bfloat16*)a1l,
        (const __nv_bfloat16*)wh1, (const __nv_bfloat16*)wl1,
        (const float*)b1, HDIM, HDIM, 1,
        (__nv_bfloat16*)a2h, (__nv_bfloat16*)a2l, nullptr);

    // join: wh2/wl2 ready
    cudaStreamWaitEvent(0, ev_w2, 0);
    gemm_split_bf16<2><<<dim3(DOUT / BN, BDIM / 64), NT, SMEM_M2>>>(
        (const __nv_bfloat16*)a2h, (const __nv_bfloat16*)a2l,
        (const __nv_bfloat16*)wh2, (const __nv_bfloat16*)wl2,
        (const float*)b2, HDIM, DOUT, 0,
        nullptr, nullptr, (float*)d_out);

    // softmax in place
    softmax_kernel<<<BDIM, 256>>>((float*)d_out);
}

// round 17
// speedup vs baseline: 3.2107x; 1.0139x over previous
#include <cuda_runtime.h>
#include <cuda_bf16.h>
#include <cstdint>
#include <cstddef>

// ---------------------------------------------------------------------------
// Problem dims
// ---------------------------------------------------------------------------
#define BDIM   8192
#define DIN    2048
#define HDIM   2048
#define DOUT   1024
#define NCOMP  4

// ---------------------------------------------------------------------------
// Helpers (sm_103-safe)
// ---------------------------------------------------------------------------
__device__ __forceinline__ uint32_t smem_u32(const void* p) {
    uint32_t a;
    asm("{ .reg .u64 t; cvta.to.shared.u64 t, %1; cvt.u32.u64 %0, t; }"
        : "=r"(a) : "l"(p));
    return a;
}

#define SMEM_SWIZZLE_128B(o) ((o) ^ (((o) >> 3) & 0x70))

__device__ __forceinline__ void cp_async16(uint32_t dst, const void* src) {
    asm volatile("cp.async.cg.shared.global [%0], [%1], 16;"
                 :: "r"(dst), "l"(__cvta_generic_to_global(src)));
}
#define CP_COMMIT() asm volatile("cp.async.commit_group;" ::: "memory")
#define CP_WAIT(n)  asm volatile("cp.async.wait_group %0;" :: "n"(n) : "memory")

__device__ __forceinline__ void ldsm4(uint32_t* r, uint32_t addr) {
    asm volatile("ldmatrix.sync.aligned.m8n8.x4.shared.b16 {%0,%1,%2,%3}, [%4];"
                 : "=r"(r[0]), "=r"(r[1]), "=r"(r[2]), "=r"(r[3]) : "r"(addr));
}

__device__ __forceinline__ void mma16816(float* d, const uint32_t* a,
                                         uint32_t b0, uint32_t b1) {
    asm volatile(
        "mma.sync.aligned.m16n8k16.row.col.f32.bf16.bf16.f32 "
        "{%0,%1,%2,%3}, {%4,%5,%6,%7}, {%8,%9}, {%0,%1,%2,%3};"
        : "+f"(d[0]), "+f"(d[1]), "+f"(d[2]), "+f"(d[3])
        : "r"(a[0]), "r"(a[1]), "r"(a[2]), "r"(a[3]), "r"(b0), "r"(b1));
}

// ---------------------------------------------------------------------------
// Scratch buffers (__device__ globals; no cudaMalloc allowed)
// ---------------------------------------------------------------------------
__device__ __align__(16) __nv_bfloat16 g_wh0[HDIM * DIN];
__device__ __align__(16) __nv_bfloat16 g_wl0[HDIM * DIN];
__device__ __align__(16) __nv_bfloat16 g_wh1[HDIM * HDIM];
__device__ __align__(16) __nv_bfloat16 g_wl1[HDIM * HDIM];
__device__ __align__(16) __nv_bfloat16 g_wh2[DOUT * HDIM];
__device__ __align__(16) __nv_bfloat16 g_wl2[DOUT * HDIM];
__device__ __align__(16) float g_b0[HDIM];
__device__ __align__(16) float g_b1[HDIM];
__device__ __align__(16) float g_b2[DOUT];
__device__ __align__(16) __nv_bfloat16 g_a0h[BDIM * DIN];
__device__ __align__(16) __nv_bfloat16 g_a0l[BDIM * DIN];
__device__ __align__(16) __nv_bfloat16 g_a1h[BDIM * HDIM];
__device__ __align__(16) __nv_bfloat16 g_a1l[BDIM * HDIM];
__device__ __align__(16) __nv_bfloat16 g_a2h[BDIM * HDIM];
__device__ __align__(16) __nv_bfloat16 g_a2l[BDIM * HDIM];

// ---------------------------------------------------------------------------
// Prep: fold mixture into effective bf16 hi/lo weights + fp32 bias
// ---------------------------------------------------------------------------
__device__ __forceinline__ void mix_coefs(const float* ml, const float* lv,
                                          float* cmu, float* cn) {
    float m[NCOMP], mx = -1e30f, s = 0.f, e[NCOMP];
    #pragma unroll
    for (int k = 0; k < NCOMP; k++) { m[k] = ml[k]; mx = fmaxf(mx, m[k]); }
    #pragma unroll
    for (int k = 0; k < NCOMP; k++) { e[k] = expf(m[k] - mx); s += e[k]; }
    #pragma unroll
    for (int k = 0; k < NCOMP; k++) {
        float w = e[k] / s;
        cmu[k] = w;
        cn[k]  = w * expf(0.5f * lv[k]);
    }
}

__device__ __forceinline__ void split_store(const float4 acc,
                                            __nv_bfloat16* whi,
                                            __nv_bfloat16* wlo, size_t i) {
    __nv_bfloat16 h0 = __float2bfloat16(acc.x);
    __nv_bfloat16 h1 = __float2bfloat16(acc.y);
    __nv_bfloat16 h2 = __float2bfloat16(acc.z);
    __nv_bfloat16 h3 = __float2bfloat16(acc.w);
    __nv_bfloat16 l0 = __float2bfloat16(acc.x - __bfloat162float(h0));
    __nv_bfloat16 l1 = __float2bfloat16(acc.y - __bfloat162float(h1));
    __nv_bfloat16 l2 = __float2bfloat16(acc.z - __bfloat162float(h2));
    __nv_bfloat16 l3 = __float2bfloat16(acc.w - __bfloat162float(h3));
    ((__nv_bfloat162*)whi)[2 * i]     = __halves2bfloat162(h0, h1);
    ((__nv_bfloat162*)whi)[2 * i + 1] = __halves2bfloat162(h2, h3);
    ((__nv_bfloat162*)wlo)[2 * i]     = __halves2bfloat162(l0, l1);
    ((__nv_bfloat162*)wlo)[2 * i + 1] = __halves2bfloat162(l2, l3);
}

__device__ __forceinline__ float4 mix4(const float4* wmu, const float4* wn,
                                       size_t n4, size_t i,
                                       const float* cmu, const float* cn) {
    float4 acc = make_float4(0.f, 0.f, 0.f, 0.f);
    #pragma unroll
    for (int k = 0; k < NCOMP; k++) {
        float4 a = wmu[(size_t)k * n4 + i];
        float4 b = wn[(size_t)k * n4 + i];
        acc.x += cmu[k] * a.x + cn[k] * b.x;
        acc.y += cmu[k] * a.y + cn[k] * b.y;
        acc.z += cmu[k] * a.z + cn[k] * b.z;
        acc.w += cmu[k] * a.w + cn[k] * b.w;
    }
    return acc;
}

// Per-layer weight fold (2 float4/thread ILP)
__global__ void prep_weights_kernel(const float* __restrict__ wmu,
                                    const float* __restrict__ wn,
                                    const float* __restrict__ wlv,
                                    const float* __restrict__ ml,
                                    __nv_bfloat16* __restrict__ whi,
                                    __nv_bfloat16* __restrict__ wlo,
                                    int n) {
    __shared__ float cmu[NCOMP], cn[NCOMP];
    if (threadIdx.x == 0) mix_coefs(ml, wlv, cmu, cn);
    __syncthreads();
    size_t n4 = (size_t)(n >> 2);
    size_t stride = (size_t)gridDim.x * blockDim.x;
    for (size_t i = (size_t)blockIdx.x * blockDim.x + threadIdx.x; i < n4;
         i += 2 * stride) {
        size_t j = i + stride;
        float4 a0 = mix4((const float4*)wmu, (const float4*)wn, n4, i, cmu, cn);
        if (j < n4) {
            float4 a1 = mix4((const float4*)wmu, (const float4*)wn, n4, j, cmu, cn);
            split_store(a0, whi, wlo, i);
            split_store(a1, whi, wlo, j);
        } else {
            split_store(a0, whi, wlo, i);
        }
    }
}

__global__ void prep_bias_all_kernel(
    const float* __restrict__ bmu0, const float* __restrict__ bn0,
    const float* __restrict__ blv0, const float* __restrict__ ml0,
    const float* __restrict__ bmu1, const float* __restrict__ bn1,
    const float* __restrict__ blv1, const float* __restrict__ ml1,
    const float* __restrict__ bmu2, const float* __restrict__ bn2,
    const float* __restrict__ blv2, const float* __restrict__ ml2,
    float* __restrict__ b0, float* __restrict__ b1, float* __restrict__ b2) {
    __shared__ float cmu[NCOMP], cn[NCOMP];
    int g = blockIdx.x * blockDim.x + threadIdx.x;
    const float* bmu; const float* bn; const float* blv; const float* ml;
    float* out; int o; int O;
    if (g < HDIM)          { bmu = bmu0; bn = bn0; blv = blv0; ml = ml0; out = b0; o = g;            O = HDIM; }
    else if (g < 2 * HDIM) { bmu = bmu1; bn = bn1; blv = blv1; ml = ml1; out = b1; o = g - HDIM;     O = HDIM; }
    else                   { bmu = bmu2; bn = bn2; blv = blv2; ml = ml2; out = b2; o = g - 2 * HDIM; O = DOUT; }
    if (threadIdx.x == 0) mix_coefs(ml, blv, cmu, cn);
    __syncthreads();
    float e = 0.f;
    #pragma unroll
    for (int k = 0; k < NCOMP; k++)
        e += cmu[k] * bmu[k * O + o] + cn[k] * bn[k * O + o];
    out[o] = e;
}

__global__ void split_x_kernel(const float* __restrict__ x,
                               __nv_bfloat16* __restrict__ xh,
                               __nv_bfloat16* __restrict__ xl, int n) {
    size_t n4 = (size_t)(n >> 2);
    size_t stride = (size_t)gridDim.x * blockDim.x;
    for (size_t i = (size_t)blockIdx.x * blockDim.x + threadIdx.x; i < n4;
         i += 2 * stride) {
        size_t j = i + stride;
        float4 v0 = ((const float4*)x)[i];
        if (j < n4) {
            float4 v1 = ((const float4*)x)[j];
            split_store(v0, xh, xl, i);
            split_store(v1, xh, xl, j);
        } else {
            split_store(v0, xh, xl, i);
        }
    }
}

// ---------------------------------------------------------------------------
// mma.sync GEMM — EXACT R15/R16 winner: MFRAG=2, 64x128 tile, 2-stage
// pipeline, one barrier/iter, __launch_bounds__(256, 2) -> 2 CTAs/SM.
// ---------------------------------------------------------------------------
#define BN 128
#define BK 64
#define NT 256

template <int MFRAG>
__global__ void __launch_bounds__(NT, (MFRAG == 2 ? 2 : 1))
gemm_split_bf16(const __nv_bfloat16* __restrict__ Ah,
                const __nv_bfloat16* __restrict__ Al,
                const __nv_bfloat16* __restrict__ Wh,
                const __nv_bfloat16* __restrict__ Wl,
                const float* __restrict__ bias,
                int Idim, int Odim, int relu_split,
                __nv_bfloat16* __restrict__ Oh,
                __nv_bfloat16* __restrict__ Ol,
                float* __restrict__ Of) {
    constexpr int BM = MFRAG * 32;
    constexpr int OFF_AL = BM * 128;
    constexpr int OFF_WH = 2 * BM * 128;
    constexpr int OFF_WL = 2 * BM * 128 + 16384;
    constexpr int STAGE  = 2 * BM * 128 + 32768;

    extern __shared__ char smem[];
    const uint32_t sb = smem_u32(smem);
    const int tid = threadIdx.x;
    const int wid = tid >> 5, l = tid & 31;
    const int n0 = blockIdx.x * BN, m0 = blockIdx.y * BM;
    const int wm = (wid >> 2) * (MFRAG * 16);
    const int wn = (wid & 3) * 32;
    const int lm = l >> 3, lr = l & 7;

    float acc[MFRAG][4][4];
    #pragma unroll
    for (int i = 0; i < MFRAG; i++)
        #pragma unroll
        for (int j = 0; j < 4; j++)
            #pragma unroll
            for (int q = 0; q < 4; q++) acc[i][j][q] = 0.f;

    const int nk = Idim / BK;

    auto issue = [&](int s, int k0) {
        uint32_t base = sb + s * STAGE;
        #pragma unroll
        for (int j = 0; j < MFRAG; j++) {
            int c = tid + j * NT;
            int row = c >> 3, col = c & 7;
            uint32_t so = SMEM_SWIZZLE_128B((uint32_t)(row * 128 + col * 16));
            size_t g = (size_t)(m0 + row) * Idim + k0 + col * 8;
            cp_async16(base + so, Ah + g);
            cp_async16(base + OFF_AL + so, Al + g);
        }
        #pragma unroll
        for (int j = 0; j < 4; j++) {
            int c = tid + j * NT;
            int row = c >> 3, col = c & 7;
            uint32_t so = SMEM_SWIZZLE_128B((uint32_t)(row * 128 + col * 16));
            size_t g = (size_t)(n0 + row) * Idim + k0 + col * 8;
            cp_async16(base + OFF_WH + so, Wh + g);
            cp_async16(base + OFF_WL + so, Wl + g);
        }
    };

    issue(0, 0);
    CP_COMMIT();

    for (int it = 0; it < nk; ++it) {
        CP_WAIT(0);
        __syncthreads();
        if (it + 1 < nk) {
            issue((it + 1) & 1, (it + 1) * BK);
            CP_COMMIT();
        }

        uint32_t bA = sb + (it & 1) * STAGE;
        #pragma unroll
        for (int kk = 0; kk < 4; kk++) {
            uint32_t ah[MFRAG][4], al[MFRAG][4];
            #pragma unroll
            for (int mf = 0; mf < MFRAG; mf++) {
                uint32_t off = SMEM_SWIZZLE_128B(
                    (uint32_t)((wm + mf * 16 + (lm & 1) * 8 + lr) * 128 +
                               (kk * 2 + (lm >> 1)) * 16));
                ldsm4(ah[mf], bA + off);
                ldsm4(al[mf], bA + OFF_AL + off);
            }
            #pragma unroll
            for (int nf2 = 0; nf2 < 2; nf2++) {
                uint32_t off = SMEM_SWIZZLE_128B(
                    (uint32_t)((wn + nf2 * 16 + (lm >> 1) * 8 + lr) * 128 +
                               (kk * 2 + (lm & 1)) * 16));
                uint32_t bh[4], bl[4];
                ldsm4(bh, bA + OFF_WH + off);
                ldsm4(bl, bA + OFF_WL + off);
                #pragma unroll
                for (int mf = 0; mf < MFRAG; mf++) {
                    mma16816(acc[mf][2 * nf2],     ah[mf], bh[0], bh[1]);
                    mma16816(acc[mf][2 * nf2 + 1], ah[mf], bh[2], bh[3]);
                }
                #pragma unroll
                for (int mf = 0; mf < MFRAG; mf++) {
                    mma16816(acc[mf][2 * nf2],     ah[mf], bl[0], bl[1]);
                    mma16816(acc[mf][2 * nf2 + 1], ah[mf], bl[2], bl[3]);
                }
                #pragma unroll
                for (int mf = 0; mf < MFRAG; mf++) {
                    mma16816(acc[mf][2 * nf2],     al[mf], bh[0], bh[1]);
                    mma16816(acc[mf][2 * nf2 + 1], al[mf], bh[2], bh[3]);
                }
            }
        }
    }

    // Epilogue
    const int cb = n0 + wn;
    if (relu_split) {
        #pragma unroll
        for (int mf = 0; mf < MFRAG; mf++) {
            int r0 = m0 + wm + mf * 16 + (l >> 2);
            #pragma unroll
            for (int nf = 0; nf < 4; nf++) {
                int col = cb + nf * 8 + 2 * (l & 3);
                float2 bv = *(const float2*)(bias + col);
                float v0 = fmaxf(acc[mf][nf][0] + bv.x, 0.f);
                float v1 = fmaxf(acc[mf][nf][1] + bv.y, 0.f);
                float v2 = fmaxf(acc[mf][nf][2] + bv.x, 0.f);
                float v3 = fmaxf(acc[mf][nf][3] + bv.y, 0.f);
                __nv_bfloat16 h0 = __float2bfloat16(v0);
                __nv_bfloat16 h1 = __float2bfloat16(v1);
                __nv_bfloat16 h2 = __float2bfloat16(v2);
                __nv_bfloat16 h3 = __float2bfloat16(v3);
                __nv_bfloat16 q0 = __float2bfloat16(v0 - __bfloat162float(h0));
                __nv_bfloat16 q1 = __float2bfloat16(v1 - __bfloat162float(h1));
                __nv_bfloat16 q2 = __float2bfloat16(v2 - __bfloat162float(h2));
                __nv_bfloat16 q3 = __float2bfloat16(v3 - __bfloat162float(h3));
                *(__nv_bfloat162*)(Oh + (size_t)r0 * Odim + col) = __halves2bfloat162(h0, h1);
                *(__nv_bfloat162*)(Oh + (size_t)(r0 + 8) * Odim + col) = __halves2bfloat162(h2, h3);
                *(__nv_bfloat162*)(Ol + (size_t)r0 * Odim + col) = __halves2bfloat162(q0, q1);
                *(__nv_bfloat162*)(Ol + (size_t)(r0 + 8) * Odim + col) = __halves2bfloat162(q2, q3);
            }
        }
    } else {
        #pragma unroll
        for (int mf = 0; mf < MFRAG; mf++) {
            int r0 = m0 + wm + mf * 16 + (l >> 2);
            #pragma unroll
            for (int nf = 0; nf < 4; nf++) {
                int col = cb + nf * 8 + 2 * (l & 3);
                float2 bv = *(const float2*)(bias + col);
                float2 o0 = make_float2(acc[mf][nf][0] + bv.x, acc[mf][nf][1] + bv.y);
                float2 o1 = make_float2(acc[mf][nf][2] + bv.x, acc[mf][nf][3] + bv.y);
                *(float2*)(Of + (size_t)r0 * Odim + col) = o0;
                *(float2*)(Of + (size_t)(r0 + 8) * Odim + col) = o1;
            }
        }
    }
}

#define SMEM_M2 (2 * (2 * 64 * 128 + 32768))    // 96 KB -> 2 CTAs/SM

// ---------------------------------------------------------------------------
// Row softmax (in-place), 1024 cols, 256 threads/row, float4 I/O
// ---------------------------------------------------------------------------
__global__ void softmax_kernel(float* __restrict__ io) {
    __shared__ float red[8];
    int b = blockIdx.x;
    float* row = io + (size_t)b * DOUT;
    int t = threadIdx.x;
    float4 v = ((const float4*)row)[t];
    float m = fmaxf(fmaxf(v.x, v.y), fmaxf(v.z, v.w));
    #pragma unroll
    for (int o = 16; o; o >>= 1) m = fmaxf(m, __shfl_xor_sync(0xffffffffu, m, o));
    if ((t & 31) == 0) red[t >> 5] = m;
    __syncthreads();
    m = red[0];
    #pragma unroll
    for (int w = 1; w < 8; w++) m = fmaxf(m, red[w]);
    v.x = expf(v.x - m); v.y = expf(v.y - m);
    v.z = expf(v.z - m); v.w = expf(v.w - m);
    float s = v.x + v.y + v.z + v.w;
    #pragma unroll
    for (int o = 16; o; o >>= 1) s += __shfl_xor_sync(0xffffffffu, s, o);
    __syncthreads();
    if ((t & 31) == 0) red[t >> 5] = s;
    __syncthreads();
    s = red[0];
    #pragma unroll
    for (int w = 1; w < 8; w++) s += red[w];
    float inv = 1.0f / s;
    v.x *= inv; v.y *= inv; v.z *= inv; v.w *= inv;
    ((float4*)row)[t] = v;
}

// ---------------------------------------------------------------------------
// Launcher — fork/join: side stream runs split_x + prep_w1 + prep_w2 while
// the main stream runs prep_w0 + biases; joins before gemm0/gemm1/gemm2.
// split_x ∥ prep_w0 overlaps two ~65%-HBM kernels into one BW-saturated window.
// ---------------------------------------------------------------------------
extern "C" void kernel_launch(void* const* d_in, const int* in_sizes, int n_in,
                              void* d_out, int out_size) {
    (void)in_sizes; (void)n_in; (void)out_size;
    const float* x   = (const float*)d_in[0];
    const float* wmu[3] = {(const float*)d_in[1],  (const float*)d_in[8],  (const float*)d_in[15]};
    const float* bmu[3] = {(const float*)d_in[2],  (const float*)d_in[9],  (const float*)d_in[16]};
    const float* wlv[3] = {(const float*)d_in[3],  (const float*)d_in[10], (const float*)d_in[17]};
    const float* blv[3] = {(const float*)d_in[4],  (const float*)d_in[11], (const float*)d_in[18]};
    const float* ml[3]  = {(const float*)d_in[5],  (const float*)d_in[12], (const float*)d_in[19]};
    const float* wn[3]  = {(const float*)d_in[6],  (const float*)d_in[13], (const float*)d_in[20]};
    const float* bn[3]  = {(const float*)d_in[7],  (const float*)d_in[14], (const float*)d_in[21]};

    void *wh0, *wl0, *wh1, *wl1, *wh2, *wl2, *b0, *b1, *b2;
    void *a0h, *a0l, *a1h, *a1l, *a2h, *a2l;
    cudaGetSymbolAddress(&wh0, g_wh0); cudaGetSymbolAddress(&wl0, g_wl0);
    cudaGetSymbolAddress(&wh1, g_wh1); cudaGetSymbolAddress(&wl1, g_wl1);
    cudaGetSymbolAddress(&wh2, g_wh2); cudaGetSymbolAddress(&wl2, g_wl2);
    cudaGetSymbolAddress(&b0, g_b0);   cudaGetSymbolAddress(&b1, g_b1);
    cudaGetSymbolAddress(&b2, g_b2);
    cudaGetSymbolAddress(&a0h, g_a0h); cudaGetSymbolAddress(&a0l, g_a0l);
    cudaGetSymbolAddress(&a1h, g_a1h); cudaGetSymbolAddress(&a1l, g_a1l);
    cudaGetSymbolAddress(&a2h, g_a2h); cudaGetSymbolAddress(&a2l, g_a2l);

    cudaFuncSetAttribute(gemm_split_bf16<2>,
                         cudaFuncAttributeMaxDynamicSharedMemorySize, SMEM_M2);

    // One-time stream/event creation (host resources, no device memory)
    static cudaStream_t s_side = nullptr;
    static cudaEvent_t ev_fork = nullptr, ev_x = nullptr, ev_w1 = nullptr, ev_w2 = nullptr;
    if (s_side == nullptr) {
        cudaStreamCreateWithFlags(&s_side, cudaStreamNonBlocking);
        cudaEventCreateWithFlags(&ev_fork, cudaEventDisableTiming);
        cudaEventCreateWithFlags(&ev_x,   cudaEventDisableTiming);
        cudaEventCreateWithFlags(&ev_w1,  cudaEventDisableTiming);
        cudaEventCreateWithFlags(&ev_w2,  cudaEventDisableTiming);
    }

    // Fork side stream into the capture
    cudaEventRecord(ev_fork, 0);
    cudaStreamWaitEvent(s_side, ev_fork, 0);

    // Side stream: split_x (needed by gemm0), then w1, w2 folds
    split_x_kernel<<<1024, 256, 0, s_side>>>(
        x, (__nv_bfloat16*)a0h, (__nv_bfloat16*)a0l, BDIM * DIN);
    cudaEventRecord(ev_x, s_side);
    prep_weights_kernel<<<1024, 256, 0, s_side>>>(
        wmu[1], wn[1], wlv[1], ml[1],
        (__nv_bfloat16*)wh1, (__nv_bfloat16*)wl1, HDIM * HDIM);
    cudaEventRecord(ev_w1, s_side);
    prep_weights_kernel<<<1024, 256, 0, s_side>>>(
        wmu[2], wn[2], wlv[2], ml[2],
        (__nv_bfloat16*)wh2, (__nv_bfloat16*)wl2, DOUT * HDIM);
    cudaEventRecord(ev_w2, s_side);

    // Main stream: w0 fold + biases (runs concurrently with split_x)
    prep_weights_kernel<<<1024, 256>>>(
        wmu[0], wn[0], wlv[0], ml[0],
        (__nv_bfloat16*)wh0, (__nv_bfloat16*)wl0, HDIM * DIN);
    prep_bias_all_kernel<<<(2 * HDIM + DOUT) / 256, 256>>>(
        bmu[0], bn[0], blv[0], ml[0],
        bmu[1], bn[1], blv[1], ml[1],
        bmu[2], bn[2], blv[2], ml[2],
        (float*)b0, (float*)b1, (float*)b2);

    // join: a0h/a0l ready
    cudaStreamWaitEvent(0, ev_x, 0);
    // layer 0: 64x128 tile, grid (16, 128) = 2048 CTAs, 2 CTAs/SM
    gemm_split_bf16<2><<<dim3(HDIM / BN, BDIM / 64), NT, SMEM_M2>>>(
        (const __nv_bfloat16*)a0h, (const __nv_bfloat16*)a0l,
        (const __nv_bfloat16*)wh0, (const __nv_bfloat16*)wl0,
        (const float*)b0, DIN, HDIM, 1,
        (__nv_bfloat16*)a1h, (__nv_bfloat16*)a1l, nullptr);

    // join: wh1/wl1 ready
    cudaStreamWaitEvent(0, ev_w1, 0);
    gemm_split_bf16<2><<<dim3(HDIM / BN, BDIM / 64), NT, SMEM_M2>>>(
        (const __nv_bfloat16*)a1h, (const __nv_bfloat16*)a1l,
        (const __nv_bfloat16*)wh1, (const __nv_bfloat16*)wl1,
        (const float*)b1, HDIM, HDIM, 1,
        (__nv_bfloat16*)a2h, (__nv_bfloat16*)a2l, nullptr);

    // join: wh2/wl2 ready
    cudaStreamWaitEvent(0, ev_w2, 0);
    gemm_split_bf16<2><<<dim3(DOUT / BN, BDIM / 64), NT, SMEM_M2>>>(
        (const __nv_bfloat16*)a2h, (const __nv_bfloat16*)a2l,
        (const __nv_bfloat16*)wh2, (const __nv_bfloat16*)wl2,
        (const float*)b2, HDIM, DOUT, 0,
        nullptr, nullptr, (float*)d_out);

    // softmax in place
    softmax_kernel<<<BDIM, 256>>>((float*)d_out);
}